// round 3
// baseline (speedup 1.0000x reference)
#include <cuda_runtime.h>
#include <cuda_bf16.h>
#include <stdint.h>

// ---------------- problem constants ----------------
#define BATCH   16384
#define QS      1204
#define FD      7
#define ROWB    (QS*FD*4)          // 33712 bytes per batch row
#define RPC     64                 // rows per CTA
#define NCTA    (BATCH/RPC)        // 256
#define FK      600
#define FKP     640
#define NCH1    20                 // k-chunks of 32 in GEMM1
#define SA      648                // A smem stride (elements) -> conflict-free
#define S2ST    136                // stage-2 A-side stride
#define F1ST    133

// feat streaming chunks
#define CQ      172                // q per chunk (172*7*4 = 4816 B, 16B aligned)
#define CB      4816
#define CPR     7                  // chunks per row
#define TCH     (RPC*CPR)          // 448

// ---------------- smem layout (bytes) ----------------
#define OFF_AH   0
#define OFF_AL   82944             // 64*648*2
#define OFF_R2   165888
// feat phase in R2
#define OFF_RING OFF_R2            // 8*4816 = 38528
#define OFF_SS   (OFF_R2+38528)    // 2*1204*4 = 9632
#define SMEM_TOTAL (OFF_SS+9632)   // 214048
// gemm1 B double buffer in R2
#define OFF_B0H  OFF_R2
#define OFF_B0L  (OFF_R2+8192)
#define OFF_B1H  (OFF_R2+16384)
#define OFF_B1L  (OFF_R2+24576)
// stage3 in R2
#define OFF_WB   OFF_R2            // 128*32*4 = 16384 fp32
#define OFF_F2   (OFF_R2+16384)    // 64*36*4  = 9216
// stage2 in A region
#define OFF_H0H  0
#define OFF_H0L  17408
#define OFF_WH   34816             // 4*4096*2 = 32768
#define OFF_WL   67584
#define OFF_T1H  100352
#define OFF_T1L  117760
#define OFF_F1   34816             // fp32 64*133*4 = 34048, overlays W after gemm3

// ---------------- global scratch: pre-split weights ----------------
__device__ __align__(16) __nv_bfloat16 g_wAh[NCH1*4096];
__device__ __align__(16) __nv_bfloat16 g_wAl[NCH1*4096];
__device__ __align__(16) __nv_bfloat16 g_w1h[4*4096];
__device__ __align__(16) __nv_bfloat16 g_w1l[4*4096];
__device__ __align__(16) __nv_bfloat16 g_w2h[4*4096];
__device__ __align__(16) __nv_bfloat16 g_w2l[4*4096];
__device__ __align__(16) float         g_wBt[128*32];

// ---------------- helpers ----------------
__device__ __forceinline__ void split_bf16(float v, __nv_bfloat16& hi, __nv_bfloat16& lo) {
    hi = __float2bfloat16(v);
    lo = __float2bfloat16(v - __bfloat162float(hi));
}
__device__ __forceinline__ uint32_t pack_bf2(__nv_bfloat16 e0, __nv_bfloat16 e1) {
    return ((uint32_t)__bfloat16_as_ushort(e1) << 16) | (uint32_t)__bfloat16_as_ushort(e0);
}
__device__ __forceinline__ uint32_t smem_u32(const void* p) {
    return (uint32_t)__cvta_generic_to_shared(p);
}
__device__ __forceinline__ void mbar_init(uint32_t mbar, uint32_t cnt) {
    asm volatile("mbarrier.init.shared.b64 [%0], %1;" :: "r"(mbar), "r"(cnt) : "memory");
}
__device__ __forceinline__ void mbar_expect_tx(uint32_t mbar, uint32_t bytes) {
    asm volatile("mbarrier.arrive.expect_tx.shared.b64 _, [%0], %1;" :: "r"(mbar), "r"(bytes) : "memory");
}
__device__ __forceinline__ void mbar_wait(uint32_t mbar, uint32_t parity) {
    asm volatile(
        "{\n\t.reg .pred P;\n"
        "W%=:\n\t"
        "mbarrier.try_wait.parity.acquire.cta.shared::cta.b64 P, [%0], %1, 0x989680;\n\t"
        "@P bra D%=;\n\t"
        "bra W%=;\n"
        "D%=:\n\t}"
        :: "r"(mbar), "r"(parity) : "memory");
}
__device__ __forceinline__ void bulk_in(uint32_t dst, const void* src, uint32_t bytes, uint32_t mbar) {
    asm volatile(
        "cp.async.bulk.shared::cta.global.mbarrier::complete_tx::bytes [%0], [%1], %2, [%3];"
        :: "r"(dst), "l"(src), "r"(bytes), "r"(mbar) : "memory");
}
__device__ __forceinline__ void mma16816(float* c,
    uint32_t a0, uint32_t a1, uint32_t a2, uint32_t a3, uint32_t b0, uint32_t b1)
{
    asm volatile(
        "mma.sync.aligned.m16n8k16.row.col.f32.bf16.bf16.f32 "
        "{%0,%1,%2,%3}, {%4,%5,%6,%7}, {%8,%9}, {%0,%1,%2,%3};\n"
        : "+f"(c[0]), "+f"(c[1]), "+f"(c[2]), "+f"(c[3])
        : "r"(a0), "r"(a1), "r"(a2), "r"(a3), "r"(b0), "r"(b1));
}
// swizzled B read: rows of 64B, byte-in-row rotated by 8*(n&7)
__device__ __forceinline__ uint32_t ldsB(const char* base, int n, int kloc) {
    const int byte = n * 64 + ((2 * kloc + 8 * (n & 7)) & 63);
    return *(const uint32_t*)(base + byte);
}

// ---------------- pre-split kernel ----------------
// wA -> [20][128][32] swizzled hi/lo (k padded to 640); w1/w2 -> [4][128][32]; wB -> transposed fp32
__global__ __launch_bounds__(256) void presplit_kernel(
    const float* __restrict__ wA, const float* __restrict__ w1,
    const float* __restrict__ w2, const float* __restrict__ wB)
{
    int id = blockIdx.x * 256 + threadIdx.x;
    if (id < 81920) {
        const int n = id / FKP, k = id % FKP;
        const float v = (k < FK) ? __ldg(wA + n * FK + k) : 0.f;
        __nv_bfloat16 h, l; split_bf16(v, h, l);
        const int idx = (k >> 5) * 4096 + n * 32 + (((2 * (k & 31) + 8 * (n & 7)) & 63) >> 1);
        g_wAh[idx] = h; g_wAl[idx] = l;
    } else if (id < 98304) {
        const int t = id - 81920, n = t >> 7, k = t & 127;
        __nv_bfloat16 h, l; split_bf16(__ldg(w1 + n * 128 + k), h, l);
        const int idx = (k >> 5) * 4096 + n * 32 + (((2 * (k & 31) + 8 * (n & 7)) & 63) >> 1);
        g_w1h[idx] = h; g_w1l[idx] = l;
    } else if (id < 114688) {
        const int t = id - 98304, n = t >> 7, k = t & 127;
        __nv_bfloat16 h, l; split_bf16(__ldg(w2 + n * 128 + k), h, l);
        const int idx = (k >> 5) * 4096 + n * 32 + (((2 * (k & 31) + 8 * (n & 7)) & 63) >> 1);
        g_w2h[idx] = h; g_w2l[idx] = l;
    } else if (id < 118784) {
        const int t = id - 114688, k = t >> 5, n = t & 31;
        g_wBt[k * 32 + n] = __ldg(wB + n * 128 + k);
    }
}

// ---------------- GEMM inner helpers ----------------
// warp tile 32M x 32N: mt=2, nt=4; g = lane>>2, tg = lane&3
__device__ __forceinline__ void gemm_chunk_A648(
    const __nv_bfloat16* Ah, const __nv_bfloat16* Al,
    const char* Bh, const char* Bl,
    int kbase, float (&acc)[2][4][4], int mb, int nb, int g, int tg)
{
    #pragma unroll
    for (int kk = 0; kk < 2; ++kk) {
        const int kloc = kk * 16 + 2 * tg;
        const int kg = kbase + kloc;
        uint32_t ah[2][4], al[2][4];
        #pragma unroll
        for (int mt = 0; mt < 2; ++mt) {
            const __nv_bfloat16* pa = Ah + (mb + mt * 16 + g) * SA + kg;
            ah[mt][0] = *(const uint32_t*)pa;
            ah[mt][1] = *(const uint32_t*)(pa + 8 * SA);
            ah[mt][2] = *(const uint32_t*)(pa + 8);
            ah[mt][3] = *(const uint32_t*)(pa + 8 * SA + 8);
            const __nv_bfloat16* pl = Al + (mb + mt * 16 + g) * SA + kg;
            al[mt][0] = *(const uint32_t*)pl;
            al[mt][1] = *(const uint32_t*)(pl + 8 * SA);
            al[mt][2] = *(const uint32_t*)(pl + 8);
            al[mt][3] = *(const uint32_t*)(pl + 8 * SA + 8);
        }
        #pragma unroll
        for (int nt = 0; nt < 4; ++nt) {
            const int n = nb + nt * 8 + g;
            const uint32_t bh0 = ldsB(Bh, n, kloc), bh1 = ldsB(Bh, n, kloc + 8);
            const uint32_t bl0 = ldsB(Bl, n, kloc), bl1 = ldsB(Bl, n, kloc + 8);
            #pragma unroll
            for (int mt = 0; mt < 2; ++mt) {
                mma16816(acc[mt][nt], ah[mt][0], ah[mt][1], ah[mt][2], ah[mt][3], bh0, bh1);
                mma16816(acc[mt][nt], ah[mt][0], ah[mt][1], ah[mt][2], ah[mt][3], bl0, bl1);
                mma16816(acc[mt][nt], al[mt][0], al[mt][1], al[mt][2], al[mt][3], bh0, bh1);
            }
        }
    }
}

// A-side stride 136 (H0/T1), B = chunked [4][128][32] swizzled, K = 128
__device__ __forceinline__ void gemm_128(
    const __nv_bfloat16* Ah, const __nv_bfloat16* Al,
    const char* Bh, const char* Bl,
    float (&acc)[2][4][4], int mb, int nb, int g, int tg)
{
    #pragma unroll
    for (int kk = 0; kk < 8; ++kk) {
        const int k0 = kk * 16 + 2 * tg;
        const int ch = k0 >> 5, kloc = k0 & 31;
        const char* BhC = Bh + ch * 8192;
        const char* BlC = Bl + ch * 8192;
        uint32_t ah[2][4], al[2][4];
        #pragma unroll
        for (int mt = 0; mt < 2; ++mt) {
            const __nv_bfloat16* pa = Ah + (mb + mt * 16 + g) * S2ST + k0;
            ah[mt][0] = *(const uint32_t*)pa;
            ah[mt][1] = *(const uint32_t*)(pa + 8 * S2ST);
            ah[mt][2] = *(const uint32_t*)(pa + 8);
            ah[mt][3] = *(const uint32_t*)(pa + 8 * S2ST + 8);
            const __nv_bfloat16* pl = Al + (mb + mt * 16 + g) * S2ST + k0;
            al[mt][0] = *(const uint32_t*)pl;
            al[mt][1] = *(const uint32_t*)(pl + 8 * S2ST);
            al[mt][2] = *(const uint32_t*)(pl + 8);
            al[mt][3] = *(const uint32_t*)(pl + 8 * S2ST + 8);
        }
        #pragma unroll
        for (int nt = 0; nt < 4; ++nt) {
            const int n = nb + nt * 8 + g;
            const uint32_t bh0 = ldsB(BhC, n, kloc), bh1 = ldsB(BhC, n, kloc + 8);
            const uint32_t bl0 = ldsB(BlC, n, kloc), bl1 = ldsB(BlC, n, kloc + 8);
            #pragma unroll
            for (int mt = 0; mt < 2; ++mt) {
                mma16816(acc[mt][nt], ah[mt][0], ah[mt][1], ah[mt][2], ah[mt][3], bh0, bh1);
                mma16816(acc[mt][nt], ah[mt][0], ah[mt][1], ah[mt][2], ah[mt][3], bl0, bl1);
                mma16816(acc[mt][nt], al[mt][0], al[mt][1], al[mt][2], al[mt][3], bh0, bh1);
            }
        }
    }
}

__device__ __forceinline__ void zero_acc(float (&acc)[2][4][4]) {
    #pragma unroll
    for (int a = 0; a < 2; ++a)
        #pragma unroll
        for (int b = 0; b < 4; ++b)
            #pragma unroll
            for (int c = 0; c < 4; ++c) acc[a][b][c] = 0.f;
}

__device__ __forceinline__ void store_split_pair(
    __nv_bfloat16* H, __nv_bfloat16* L, int m, int col, float v0, float v1)
{
    __nv_bfloat16 h0, l0, h1, l1;
    split_bf16(v0, h0, l0);
    split_bf16(v1, h1, l1);
    *(uint32_t*)(H + m * S2ST + col) = pack_bf2(h0, h1);
    *(uint32_t*)(L + m * S2ST + col) = pack_bf2(l0, l1);
}

// ---------------- fused kernel ----------------
__global__ __launch_bounds__(256, 1) void fused_kernel(
    const float* __restrict__ x,
    const float* __restrict__ w_step, const float* __restrict__ b_step,
    const float* __restrict__ bA,
    const float* __restrict__ b1, const float* __restrict__ b2,
    const float* __restrict__ bB,
    const float* __restrict__ wC, const float* __restrict__ bC,
    float* __restrict__ out)
{
    extern __shared__ __align__(16) char smem[];
    __shared__ __align__(8) unsigned long long mb_x[8];
    __shared__ __align__(8) unsigned long long mb_b[2];

    const int tid  = threadIdx.x;
    const int wid  = tid >> 5;
    const int lane = tid & 31;
    const int g    = lane >> 2;
    const int tg   = lane & 3;
    const int mb   = (wid & 1) * 32;
    const int nb   = (wid >> 1) * 32;
    const int row0 = blockIdx.x * RPC;

    __nv_bfloat16* Ah = (__nv_bfloat16*)(smem + OFF_AH);
    __nv_bfloat16* Al = (__nv_bfloat16*)(smem + OFF_AL);
    float* ss = (float*)(smem + OFF_SS);

    // init mbarriers + zero A k-padding
    if (tid == 0) {
        #pragma unroll
        for (int i = 0; i < 8; ++i) mbar_init(smem_u32(&mb_x[i]), 1);
        mbar_init(smem_u32(&mb_b[0]), 1);
        mbar_init(smem_u32(&mb_b[1]), 1);
    }
    for (int i = tid; i < RPC * (FKP - FK); i += 256) {
        const int r = i / (FKP - FK), j = FK + i % (FKP - FK);
        Ah[r * SA + j] = __float2bfloat16(0.f);
        Al[r * SA + j] = __float2bfloat16(0.f);
    }
    __syncthreads();

    // ---------- feat phase: TMA ring over x ----------
    const char* xbase = (const char*)x + (size_t)blockIdx.x * (RPC * (size_t)ROWB);
    const uint32_t ringu = smem_u32(smem + OFF_RING);
    if (tid == 0) {
        #pragma unroll
        for (int i = 0; i < 8; ++i) {
            const uint32_t m = smem_u32(&mb_x[i]);
            mbar_expect_tx(m, CB);
            bulk_in(ringu + i * CB, xbase + (size_t)i * CB, CB, m);
        }
    }
    const float w0 = __ldg(w_step + 0), w1c = __ldg(w_step + 1), w2c = __ldg(w_step + 2),
                w3 = __ldg(w_step + 3), w4 = __ldg(w_step + 4), w5 = __ldg(w_step + 5),
                w6 = __ldg(w_step + 6), bsv = __ldg(b_step);

    int gc = 0;
    for (int it = 0; it < TCH / 2; ++it, gc += 2) {
        int rEnd = -1;
        #pragma unroll
        for (int k2 = 0; k2 < 2; ++k2) {
            const int cc = gc + k2, s = cc & 7, ph = (cc >> 3) & 1;
            mbar_wait(smem_u32(&mb_x[s]), ph);
            const int r = cc / 7, cq = cc - r * 7;
            if (cc % 7 == 6) rEnd = r;
            if (tid < CQ) {
                const float* p = (const float*)(smem + OFF_RING + s * CB) + tid * 7;
                float v = fmaf(p[0], w0, fmaf(p[1], w1c, fmaf(p[2], w2c,
                          fmaf(p[3], w3, fmaf(p[4], w4, fmaf(p[5], w5, p[6] * w6))))));
                ss[(r & 1) * QS + cq * CQ + tid] = v + bsv;
            }
        }
        __syncthreads();
        if (tid == 0) {
            #pragma unroll
            for (int k2 = 0; k2 < 2; ++k2) {
                const int nc = gc + 8 + k2;
                if (nc < TCH) {
                    const int s = nc & 7;
                    const uint32_t m = smem_u32(&mb_x[s]);
                    mbar_expect_tx(m, CB);
                    bulk_in(ringu + s * CB, xbase + (size_t)nc * CB, CB, m);
                }
            }
        }
        if (rEnd >= 0) {
            const float* sr = ss + (rEnd & 1) * QS;
            for (int j = tid; j < FK; j += 256) {
                const int bl = j / 5, off = j % 5;
                const float* p = sr + off + bl * 10;
                float m = p[0];
                #pragma unroll
                for (int i = 1; i < 10; ++i) m = fmaxf(m, p[i]);
                __nv_bfloat16 h, l; split_bf16(m, h, l);
                Ah[rEnd * SA + j] = h;
                Al[rEnd * SA + j] = l;
            }
        }
    }
    __syncthreads();

    // ---------- GEMM1: h0 = relu(feat @ wA^T + bA) ----------
    float acc[2][4][4];
    zero_acc(acc);
    {
        const uint32_t b0h = smem_u32(smem + OFF_B0H);
        if (tid == 0) {
            #pragma unroll
            for (int c = 0; c < 2; ++c) {
                const uint32_t m = smem_u32(&mb_b[c]);
                mbar_expect_tx(m, 16384);
                bulk_in(b0h + c * 16384,        (const char*)g_wAh + c * 8192, 8192, m);
                bulk_in(b0h + c * 16384 + 8192, (const char*)g_wAl + c * 8192, 8192, m);
            }
        }
        for (int c = 0; c < NCH1; ++c) {
            const int buf = c & 1;
            mbar_wait(smem_u32(&mb_b[buf]), (c >> 1) & 1);
            gemm_chunk_A648(Ah, Al,
                            smem + OFF_B0H + buf * 16384,
                            smem + OFF_B0H + buf * 16384 + 8192,
                            c * 32, acc, mb, nb, g, tg);
            __syncthreads();
            if (tid == 0 && c + 2 < NCH1) {
                const int nc = c + 2;
                const uint32_t m = smem_u32(&mb_b[buf]);
                mbar_expect_tx(m, 16384);
                bulk_in(b0h + buf * 16384,        (const char*)g_wAh + nc * 8192, 8192, m);
                bulk_in(b0h + buf * 16384 + 8192, (const char*)g_wAl + nc * 8192, 8192, m);
            }
        }
    }

    // epilogue 1: h0 -> split bf16 H0 (A region now dead)
    __nv_bfloat16* H0h = (__nv_bfloat16*)(smem + OFF_H0H);
    __nv_bfloat16* H0l = (__nv_bfloat16*)(smem + OFF_H0L);
    #pragma unroll
    for (int mt = 0; mt < 2; ++mt) {
        const int m0 = mb + mt * 16 + g;
        #pragma unroll
        for (int nt = 0; nt < 4; ++nt) {
            const int col = nb + nt * 8 + 2 * tg;
            const float bb0 = __ldg(bA + col), bb1 = __ldg(bA + col + 1);
            store_split_pair(H0h, H0l, m0,     col,
                             fmaxf(acc[mt][nt][0] + bb0, 0.f),
                             fmaxf(acc[mt][nt][1] + bb1, 0.f));
            store_split_pair(H0h, H0l, m0 + 8, col,
                             fmaxf(acc[mt][nt][2] + bb0, 0.f),
                             fmaxf(acc[mt][nt][3] + bb1, 0.f));
        }
    }
    // copy w1 hi/lo + wB (plain, L2-resident)
    {
        uint4* dh = (uint4*)(smem + OFF_WH);
        uint4* dl = (uint4*)(smem + OFF_WL);
        const uint4* sh = (const uint4*)g_w1h;
        const uint4* sl = (const uint4*)g_w1l;
        #pragma unroll 4
        for (int i = tid; i < 2048; i += 256) { dh[i] = sh[i]; dl[i] = sl[i]; }
        float4* wb = (float4*)(smem + OFF_WB);
        const float4* ws = (const float4*)g_wBt;
        #pragma unroll 2
        for (int i = tid; i < 1024; i += 256) wb[i] = ws[i];
    }
    __syncthreads();

    // ---------- GEMM2: t1 = relu(h0 @ w1^T + b1) ----------
    zero_acc(acc);
    gemm_128(H0h, H0l, smem + OFF_WH, smem + OFF_WL, acc, mb, nb, g, tg);
    {
        __nv_bfloat16* T1h = (__nv_bfloat16*)(smem + OFF_T1H);
        __nv_bfloat16* T1l = (__nv_bfloat16*)(smem + OFF_T1L);
        #pragma unroll
        for (int mt = 0; mt < 2; ++mt) {
            const int m0 = mb + mt * 16 + g;
            #pragma unroll
            for (int nt = 0; nt < 4; ++nt) {
                const int col = nb + nt * 8 + 2 * tg;
                const float bb0 = __ldg(b1 + col), bb1 = __ldg(b1 + col + 1);
                store_split_pair(T1h, T1l, m0,     col,
                                 fmaxf(acc[mt][nt][0] + bb0, 0.f),
                                 fmaxf(acc[mt][nt][1] + bb1, 0.f));
                store_split_pair(T1h, T1l, m0 + 8, col,
                                 fmaxf(acc[mt][nt][2] + bb0, 0.f),
                                 fmaxf(acc[mt][nt][3] + bb1, 0.f));
            }
        }
    }
    __syncthreads();
    // copy w2 hi/lo over w1
    {
        uint4* dh = (uint4*)(smem + OFF_WH);
        uint4* dl = (uint4*)(smem + OFF_WL);
        const uint4* sh = (const uint4*)g_w2h;
        const uint4* sl = (const uint4*)g_w2l;
        #pragma unroll 4
        for (int i = tid; i < 2048; i += 256) { dh[i] = sh[i]; dl[i] = sl[i]; }
    }
    __syncthreads();

    // ---------- GEMM3: h1 = relu(h0 + t1 @ w2^T + b2) -> fp32 F1 ----------
    zero_acc(acc);
    gemm_128((__nv_bfloat16*)(smem + OFF_T1H), (__nv_bfloat16*)(smem + OFF_T1L),
             smem + OFF_WH, smem + OFF_WL, acc, mb, nb, g, tg);
    __syncthreads();   // all W reads done before F1 overlays W
    {
        float* F1 = (float*)(smem + OFF_F1);
        #pragma unroll
        for (int mt = 0; mt < 2; ++mt) {
            const int m0 = mb + mt * 16 + g;
            #pragma unroll
            for (int nt = 0; nt < 4; ++nt) {
                const int col = nb + nt * 8 + 2 * tg;
                const float bb0 = __ldg(b2 + col), bb1 = __ldg(b2 + col + 1);
                const float h00 = __bfloat162float(H0h[m0 * S2ST + col])
                                + __bfloat162float(H0l[m0 * S2ST + col]);
                const float h01 = __bfloat162float(H0h[m0 * S2ST + col + 1])
                                + __bfloat162float(H0l[m0 * S2ST + col + 1]);
                const float h10 = __bfloat162float(H0h[(m0 + 8) * S2ST + col])
                                + __bfloat162float(H0l[(m0 + 8) * S2ST + col]);
                const float h11 = __bfloat162float(H0h[(m0 + 8) * S2ST + col + 1])
                                + __bfloat162float(H0l[(m0 + 8) * S2ST + col + 1]);
                F1[m0 * F1ST + col]           = fmaxf(h00 + acc[mt][nt][0] + bb0, 0.f);
                F1[m0 * F1ST + col + 1]       = fmaxf(h01 + acc[mt][nt][1] + bb1, 0.f);
                F1[(m0 + 8) * F1ST + col]     = fmaxf(h10 + acc[mt][nt][2] + bb0, 0.f);
                F1[(m0 + 8) * F1ST + col + 1] = fmaxf(h11 + acc[mt][nt][3] + bb1, 0.f);
            }
        }
    }
    __syncthreads();

    // ---------- Stage 3: h2 = relu(h1 @ wB^T + bB) ----------
    {
        const float* F1 = (const float*)(smem + OFF_F1);
        const float* wBs = (const float*)(smem + OFF_WB);
        float* F2 = (float*)(smem + OFF_F2);
        const int r  = tid >> 2;
        const int n0 = (tid & 3) * 8;
        float a3[8];
        #pragma unroll
        for (int i = 0; i < 8; ++i) a3[i] = 0.f;
        #pragma unroll 4
        for (int k = 0; k < 128; ++k) {
            const float hv = F1[r * F1ST + k];
            const float4 q0 = *(const float4*)(wBs + k * 32 + n0);
            const float4 q1 = *(const float4*)(wBs + k * 32 + n0 + 4);
            a3[0] = fmaf(hv, q0.x, a3[0]); a3[1] = fmaf(hv, q0.y, a3[1]);
            a3[2] = fmaf(hv, q0.z, a3[2]); a3[3] = fmaf(hv, q0.w, a3[3]);
            a3[4] = fmaf(hv, q1.x, a3[4]); a3[5] = fmaf(hv, q1.y, a3[5]);
            a3[6] = fmaf(hv, q1.z, a3[6]); a3[7] = fmaf(hv, q1.w, a3[7]);
        }
        #pragma unroll
        for (int n = 0; n < 8; ++n)
            F2[r * 36 + n0 + n] = fmaxf(a3[n] + __ldg(bB + n0 + n), 0.f);
    }
    __syncthreads();

    // ---------- Stage 4: logits ----------
    if (tid < 128) {
        const float* F2 = (const float*)(smem + OFF_F2);
        const int r = tid >> 1, c = tid & 1;
        float s = __ldg(bC + c);
        #pragma unroll
        for (int k = 0; k < 32; ++k)
            s = fmaf(F2[r * 36 + k], __ldg(wC + c * 32 + k), s);
        out[(size_t)(row0 + r) * 2 + c] = s;
    }
}

// ---------------- launch ----------------
extern "C" void kernel_launch(void* const* d_in, const int* in_sizes, int n_in,
                              void* d_out, int out_size)
{
    const float* x      = (const float*)d_in[0];
    const float* w_step = (const float*)d_in[1];
    const float* b_step = (const float*)d_in[2];
    const float* wA     = (const float*)d_in[3];
    const float* bA     = (const float*)d_in[4];
    const float* w1     = (const float*)d_in[5];
    const float* b1     = (const float*)d_in[6];
    const float* w2     = (const float*)d_in[7];
    const float* b2     = (const float*)d_in[8];
    const float* wB     = (const float*)d_in[9];
    const float* bB     = (const float*)d_in[10];
    const float* wC     = (const float*)d_in[11];
    const float* bC     = (const float*)d_in[12];
    float* out          = (float*)d_out;

    cudaFuncSetAttribute(fused_kernel, cudaFuncAttributeMaxDynamicSharedMemorySize, SMEM_TOTAL);

    presplit_kernel<<<464, 256>>>(wA, w1, w2, wB);
    fused_kernel<<<NCTA, 256, SMEM_TOTAL>>>(x, w_step, b_step, bA, b1, b2, bB, wC, bC, out);
}

// round 5
// speedup vs baseline: 1.0002x; 1.0002x over previous
#include <cuda_runtime.h>
#include <cuda_bf16.h>
#include <stdint.h>

// ---------------- problem constants ----------------
#define BATCH   16384
#define QS      1204
#define FD      7
#define ROWB    (QS*FD*4)          // 33712 bytes per batch row
#define RPC     64                 // rows per CTA
#define NCTA    (BATCH/RPC)        // 256
#define FK      600
#define FKP     640
#define NCH1    20                 // k-chunks of 32 in GEMM1
#define SA      648                // A smem stride (elements) -> conflict-free
#define S2ST    136                // stage-2 A-side stride
#define F1ST    133

// feat streaming chunks
#define CQ      172                // q per chunk (172*7*4 = 4816 B, 16B aligned)
#define CB      4816
#define CPR     7                  // chunks per row
#define TCH     (RPC*CPR)          // 448

// ---------------- smem layout (bytes) ----------------
#define OFF_AH   0
#define OFF_AL   82944             // 64*648*2
#define OFF_R2   165888
// feat phase in R2
#define OFF_RING OFF_R2            // 8*4816 = 38528
#define OFF_SS   (OFF_R2+38528)    // 2*1204*4 = 9632
#define SMEM_TOTAL (OFF_SS+9632)   // 214048
// gemm1 B double buffer in R2
#define OFF_B0H  OFF_R2
// stage3 in R2
#define OFF_WB   OFF_R2            // 128*32*4 = 16384 fp32
#define OFF_F2   (OFF_R2+16384)    // 64*36*4  = 9216
// stage2 in A region
#define OFF_H0H  0
#define OFF_H0L  17408
#define OFF_WH   34816             // 4*4096*2 = 32768
#define OFF_WL   67584
#define OFF_T1H  100352
#define OFF_T1L  117760
#define OFF_F1   34816             // fp32 64*133*4 = 34048, overlays W after gemm3

// ---------------- global scratch: pre-split weights ----------------
__device__ __align__(16) __nv_bfloat16 g_wAh[NCH1*4096];
__device__ __align__(16) __nv_bfloat16 g_wAl[NCH1*4096];
__device__ __align__(16) __nv_bfloat16 g_w1h[4*4096];
__device__ __align__(16) __nv_bfloat16 g_w1l[4*4096];
__device__ __align__(16) __nv_bfloat16 g_w2h[4*4096];
__device__ __align__(16) __nv_bfloat16 g_w2l[4*4096];
__device__ __align__(16) float         g_wBt[128*32];

// ---------------- helpers ----------------
__device__ __forceinline__ void split_bf16(float v, __nv_bfloat16& hi, __nv_bfloat16& lo) {
    hi = __float2bfloat16(v);
    lo = __float2bfloat16(v - __bfloat162float(hi));
}
__device__ __forceinline__ uint32_t pack_bf2(__nv_bfloat16 e0, __nv_bfloat16 e1) {
    return ((uint32_t)__bfloat16_as_ushort(e1) << 16) | (uint32_t)__bfloat16_as_ushort(e0);
}
__device__ __forceinline__ uint32_t smem_u32(const void* p) {
    return (uint32_t)__cvta_generic_to_shared(p);
}
__device__ __forceinline__ void mbar_init(uint32_t mbar, uint32_t cnt) {
    asm volatile("mbarrier.init.shared.b64 [%0], %1;" :: "r"(mbar), "r"(cnt) : "memory");
}
__device__ __forceinline__ void mbar_expect_tx(uint32_t mbar, uint32_t bytes) {
    asm volatile("mbarrier.arrive.expect_tx.shared.b64 _, [%0], %1;" :: "r"(mbar), "r"(bytes) : "memory");
}
__device__ __forceinline__ void mbar_wait(uint32_t mbar, uint32_t parity) {
    asm volatile(
        "{\n\t.reg .pred P;\n"
        "W%=:\n\t"
        "mbarrier.try_wait.parity.acquire.cta.shared::cta.b64 P, [%0], %1, 0x989680;\n\t"
        "@P bra D%=;\n\t"
        "bra W%=;\n"
        "D%=:\n\t}"
        :: "r"(mbar), "r"(parity) : "memory");
}
__device__ __forceinline__ void bulk_in(uint32_t dst, const void* src, uint32_t bytes, uint32_t mbar) {
    asm volatile(
        "cp.async.bulk.shared::cta.global.mbarrier::complete_tx::bytes [%0], [%1], %2, [%3];"
        :: "r"(dst), "l"(src), "r"(bytes), "r"(mbar) : "memory");
}
__device__ __forceinline__ void mma16816(float* c,
    uint32_t a0, uint32_t a1, uint32_t a2, uint32_t a3, uint32_t b0, uint32_t b1)
{
    asm volatile(
        "mma.sync.aligned.m16n8k16.row.col.f32.bf16.bf16.f32 "
        "{%0,%1,%2,%3}, {%4,%5,%6,%7}, {%8,%9}, {%0,%1,%2,%3};\n"
        : "+f"(c[0]), "+f"(c[1]), "+f"(c[2]), "+f"(c[3])
        : "r"(a0), "r"(a1), "r"(a2), "r"(a3), "r"(b0), "r"(b1));
}
// swizzled B read: rows of 64B, byte-in-row rotated by 8*(n&7)
__device__ __forceinline__ uint32_t ldsB(const char* base, int n, int kloc) {
    const int byte = n * 64 + ((2 * kloc + 8 * (n & 7)) & 63);
    return *(const uint32_t*)(base + byte);
}

// ---------------- pre-split kernel ----------------
// wA -> [20][128][32] swizzled hi/lo (k padded to 640); w1/w2 -> [4][128][32]; wB -> transposed fp32
__global__ __launch_bounds__(256) void presplit_kernel(
    const float* __restrict__ wA, const float* __restrict__ w1,
    const float* __restrict__ w2, const float* __restrict__ wB)
{
    int id = blockIdx.x * 256 + threadIdx.x;
    if (id < 81920) {
        const int n = id / FKP, k = id % FKP;
        const float v = (k < FK) ? __ldg(wA + n * FK + k) : 0.f;
        __nv_bfloat16 h, l; split_bf16(v, h, l);
        const int idx = (k >> 5) * 4096 + n * 32 + (((2 * (k & 31) + 8 * (n & 7)) & 63) >> 1);
        g_wAh[idx] = h; g_wAl[idx] = l;
    } else if (id < 98304) {
        const int t = id - 81920, n = t >> 7, k = t & 127;
        __nv_bfloat16 h, l; split_bf16(__ldg(w1 + n * 128 + k), h, l);
        const int idx = (k >> 5) * 4096 + n * 32 + (((2 * (k & 31) + 8 * (n & 7)) & 63) >> 1);
        g_w1h[idx] = h; g_w1l[idx] = l;
    } else if (id < 114688) {
        const int t = id - 98304, n = t >> 7, k = t & 127;
        __nv_bfloat16 h, l; split_bf16(__ldg(w2 + n * 128 + k), h, l);
        const int idx = (k >> 5) * 4096 + n * 32 + (((2 * (k & 31) + 8 * (n & 7)) & 63) >> 1);
        g_w2h[idx] = h; g_w2l[idx] = l;
    } else if (id < 118784) {
        const int t = id - 114688, k = t >> 5, n = t & 31;
        g_wBt[k * 32 + n] = __ldg(wB + n * 128 + k);
    }
}

// ---------------- GEMM inner helpers ----------------
// warp tile 32M x 32N: mt=2, nt=4; g = lane>>2, tg = lane&3
__device__ __forceinline__ void gemm_chunk_A648(
    const __nv_bfloat16* Ah, const __nv_bfloat16* Al,
    const char* Bh, const char* Bl,
    int kbase, float (&acc)[2][4][4], int mb, int nb, int g, int tg)
{
    #pragma unroll
    for (int kk = 0; kk < 2; ++kk) {
        const int kloc = kk * 16 + 2 * tg;
        const int kg = kbase + kloc;
        uint32_t ah[2][4], al[2][4];
        #pragma unroll
        for (int mt = 0; mt < 2; ++mt) {
            const __nv_bfloat16* pa = Ah + (mb + mt * 16 + g) * SA + kg;
            ah[mt][0] = *(const uint32_t*)pa;
            ah[mt][1] = *(const uint32_t*)(pa + 8 * SA);
            ah[mt][2] = *(const uint32_t*)(pa + 8);
            ah[mt][3] = *(const uint32_t*)(pa + 8 * SA + 8);
            const __nv_bfloat16* pl = Al + (mb + mt * 16 + g) * SA + kg;
            al[mt][0] = *(const uint32_t*)pl;
            al[mt][1] = *(const uint32_t*)(pl + 8 * SA);
            al[mt][2] = *(const uint32_t*)(pl + 8);
            al[mt][3] = *(const uint32_t*)(pl + 8 * SA + 8);
        }
        #pragma unroll
        for (int nt = 0; nt < 4; ++nt) {
            const int n = nb + nt * 8 + g;
            const uint32_t bh0 = ldsB(Bh, n, kloc), bh1 = ldsB(Bh, n, kloc + 8);
            const uint32_t bl0 = ldsB(Bl, n, kloc), bl1 = ldsB(Bl, n, kloc + 8);
            #pragma unroll
            for (int mt = 0; mt < 2; ++mt) {
                mma16816(acc[mt][nt], ah[mt][0], ah[mt][1], ah[mt][2], ah[mt][3], bh0, bh1);
                mma16816(acc[mt][nt], ah[mt][0], ah[mt][1], ah[mt][2], ah[mt][3], bl0, bl1);
                mma16816(acc[mt][nt], al[mt][0], al[mt][1], al[mt][2], al[mt][3], bh0, bh1);
            }
        }
    }
}

// A-side stride 136 (H0/T1), B = chunked [4][128][32] swizzled, K = 128
__device__ __forceinline__ void gemm_128(
    const __nv_bfloat16* Ah, const __nv_bfloat16* Al,
    const char* Bh, const char* Bl,
    float (&acc)[2][4][4], int mb, int nb, int g, int tg)
{
    #pragma unroll
    for (int kk = 0; kk < 8; ++kk) {
        const int k0 = kk * 16 + 2 * tg;
        const int ch = k0 >> 5, kloc = k0 & 31;
        const char* BhC = Bh + ch * 8192;
        const char* BlC = Bl + ch * 8192;
        uint32_t ah[2][4], al[2][4];
        #pragma unroll
        for (int mt = 0; mt < 2; ++mt) {
            const __nv_bfloat16* pa = Ah + (mb + mt * 16 + g) * S2ST + k0;
            ah[mt][0] = *(const uint32_t*)pa;
            ah[mt][1] = *(const uint32_t*)(pa + 8 * S2ST);
            ah[mt][2] = *(const uint32_t*)(pa + 8);
            ah[mt][3] = *(const uint32_t*)(pa + 8 * S2ST + 8);
            const __nv_bfloat16* pl = Al + (mb + mt * 16 + g) * S2ST + k0;
            al[mt][0] = *(const uint32_t*)pl;
            al[mt][1] = *(const uint32_t*)(pl + 8 * S2ST);
            al[mt][2] = *(const uint32_t*)(pl + 8);
            al[mt][3] = *(const uint32_t*)(pl + 8 * S2ST + 8);
        }
        #pragma unroll
        for (int nt = 0; nt < 4; ++nt) {
            const int n = nb + nt * 8 + g;
            const uint32_t bh0 = ldsB(BhC, n, kloc), bh1 = ldsB(BhC, n, kloc + 8);
            const uint32_t bl0 = ldsB(BlC, n, kloc), bl1 = ldsB(BlC, n, kloc + 8);
            #pragma unroll
            for (int mt = 0; mt < 2; ++mt) {
                mma16816(acc[mt][nt], ah[mt][0], ah[mt][1], ah[mt][2], ah[mt][3], bh0, bh1);
                mma16816(acc[mt][nt], ah[mt][0], ah[mt][1], ah[mt][2], ah[mt][3], bl0, bl1);
                mma16816(acc[mt][nt], al[mt][0], al[mt][1], al[mt][2], al[mt][3], bh0, bh1);
            }
        }
    }
}

__device__ __forceinline__ void zero_acc(float (&acc)[2][4][4]) {
    #pragma unroll
    for (int a = 0; a < 2; ++a)
        #pragma unroll
        for (int b = 0; b < 4; ++b)
            #pragma unroll
            for (int c = 0; c < 4; ++c) acc[a][b][c] = 0.f;
}

__device__ __forceinline__ void store_split_pair(
    __nv_bfloat16* H, __nv_bfloat16* L, int m, int col, float v0, float v1)
{
    __nv_bfloat16 h0, l0, h1, l1;
    split_bf16(v0, h0, l0);
    split_bf16(v1, h1, l1);
    *(uint32_t*)(H + m * S2ST + col) = pack_bf2(h0, h1);
    *(uint32_t*)(L + m * S2ST + col) = pack_bf2(l0, l1);
}

// ---------------- fused kernel ----------------
__global__ __launch_bounds__(256, 1) void fused_kernel(
    const float* __restrict__ x,
    const float* __restrict__ w_step, const float* __restrict__ b_step,
    const float* __restrict__ bA,
    const float* __restrict__ b1, const float* __restrict__ b2,
    const float* __restrict__ bB,
    const float* __restrict__ wC, const float* __restrict__ bC,
    float* __restrict__ out)
{
    extern __shared__ __align__(16) char smem[];
    __shared__ __align__(8) unsigned long long mb_x[8];
    __shared__ __align__(8) unsigned long long mb_b[2];

    const int tid  = threadIdx.x;
    const int wid  = tid >> 5;
    const int lane = tid & 31;
    const int g    = lane >> 2;
    const int tg   = lane & 3;
    const int mb   = (wid & 1) * 32;
    const int nb   = (wid >> 1) * 32;
    const int row0 = blockIdx.x * RPC;

    __nv_bfloat16* Ah = (__nv_bfloat16*)(smem + OFF_AH);
    __nv_bfloat16* Al = (__nv_bfloat16*)(smem + OFF_AL);
    float* ss = (float*)(smem + OFF_SS);

    // init mbarriers + zero A k-padding
    if (tid == 0) {
        #pragma unroll
        for (int i = 0; i < 8; ++i) mbar_init(smem_u32(&mb_x[i]), 1);
        mbar_init(smem_u32(&mb_b[0]), 1);
        mbar_init(smem_u32(&mb_b[1]), 1);
    }
    for (int i = tid; i < RPC * (FKP - FK); i += 256) {
        const int r = i / (FKP - FK), j = FK + i % (FKP - FK);
        Ah[r * SA + j] = __float2bfloat16(0.f);
        Al[r * SA + j] = __float2bfloat16(0.f);
    }
    __syncthreads();

    // ---------- feat phase: bulk-async ring over x ----------
    const char* xbase = (const char*)x + (size_t)blockIdx.x * (RPC * (size_t)ROWB);
    const uint32_t ringu = smem_u32(smem + OFF_RING);
    if (tid == 0) {
        #pragma unroll
        for (int i = 0; i < 8; ++i) {
            const uint32_t m = smem_u32(&mb_x[i]);
            mbar_expect_tx(m, CB);
            bulk_in(ringu + i * CB, xbase + (size_t)i * CB, CB, m);
        }
    }
    const float w0 = __ldg(w_step + 0), w1c = __ldg(w_step + 1), w2c = __ldg(w_step + 2),
                w3 = __ldg(w_step + 3), w4 = __ldg(w_step + 4), w5 = __ldg(w_step + 5),
                w6 = __ldg(w_step + 6), bsv = __ldg(b_step);

    int gc = 0;
    for (int it = 0; it < TCH / 2; ++it, gc += 2) {
        int rEnd = -1;
        #pragma unroll
        for (int k2 = 0; k2 < 2; ++k2) {
            const int cc = gc + k2, s = cc & 7, ph = (cc >> 3) & 1;
            mbar_wait(smem_u32(&mb_x[s]), ph);
            const int r = cc / 7, cq = cc - r * 7;
            if (cc % 7 == 6) rEnd = r;
            if (tid < CQ) {
                const float* p = (const float*)(smem + OFF_RING + s * CB) + tid * 7;
                float v = fmaf(p[0], w0, fmaf(p[1], w1c, fmaf(p[2], w2c,
                          fmaf(p[3], w3, fmaf(p[4], w4, fmaf(p[5], w5, p[6] * w6))))));
                ss[(r & 1) * QS + cq * CQ + tid] = v + bsv;
            }
        }
        __syncthreads();
        if (tid == 0) {
            #pragma unroll
            for (int k2 = 0; k2 < 2; ++k2) {
                const int nc = gc + 8 + k2;
                if (nc < TCH) {
                    const int s = nc & 7;
                    const uint32_t m = smem_u32(&mb_x[s]);
                    mbar_expect_tx(m, CB);
                    bulk_in(ringu + s * CB, xbase + (size_t)nc * CB, CB, m);
                }
            }
        }
        if (rEnd >= 0) {
            const float* sr = ss + (rEnd & 1) * QS;
            for (int j = tid; j < FK; j += 256) {
                const int bl = j / 5, off = j % 5;
                const float* p = sr + off + bl * 10;
                float m = p[0];
                #pragma unroll
                for (int i = 1; i < 10; ++i) m = fmaxf(m, p[i]);
                __nv_bfloat16 h, l; split_bf16(m, h, l);
                Ah[rEnd * SA + j] = h;
                Al[rEnd * SA + j] = l;
            }
        }
    }
    __syncthreads();

    // ---------- GEMM1: h0 = relu(feat @ wA^T + bA) ----------
    float acc[2][4][4];
    zero_acc(acc);
    {
        const uint32_t b0h = smem_u32(smem + OFF_B0H);
        if (tid == 0) {
            #pragma unroll
            for (int c = 0; c < 2; ++c) {
                const uint32_t m = smem_u32(&mb_b[c]);
                mbar_expect_tx(m, 16384);
                bulk_in(b0h + c * 16384,        (const char*)g_wAh + c * 8192, 8192, m);
                bulk_in(b0h + c * 16384 + 8192, (const char*)g_wAl + c * 8192, 8192, m);
            }
        }
        for (int c = 0; c < NCH1; ++c) {
            const int buf = c & 1;
            mbar_wait(smem_u32(&mb_b[buf]), (c >> 1) & 1);
            gemm_chunk_A648(Ah, Al,
                            smem + OFF_B0H + buf * 16384,
                            smem + OFF_B0H + buf * 16384 + 8192,
                            c * 32, acc, mb, nb, g, tg);
            __syncthreads();
            if (tid == 0 && c + 2 < NCH1) {
                const int nc = c + 2;
                const uint32_t m = smem_u32(&mb_b[buf]);
                mbar_expect_tx(m, 16384);
                bulk_in(b0h + buf * 16384,        (const char*)g_wAh + nc * 8192, 8192, m);
                bulk_in(b0h + buf * 16384 + 8192, (const char*)g_wAl + nc * 8192, 8192, m);
            }
        }
    }

    // epilogue 1: h0 -> split bf16 H0 (A region now dead)
    __nv_bfloat16* H0h = (__nv_bfloat16*)(smem + OFF_H0H);
    __nv_bfloat16* H0l = (__nv_bfloat16*)(smem + OFF_H0L);
    #pragma unroll
    for (int mt = 0; mt < 2; ++mt) {
        const int m0 = mb + mt * 16 + g;
        #pragma unroll
        for (int nt = 0; nt < 4; ++nt) {
            const int col = nb + nt * 8 + 2 * tg;
            const float bb0 = __ldg(bA + col), bb1 = __ldg(bA + col + 1);
            store_split_pair(H0h, H0l, m0,     col,
                             fmaxf(acc[mt][nt][0] + bb0, 0.f),
                             fmaxf(acc[mt][nt][1] + bb1, 0.f));
            store_split_pair(H0h, H0l, m0 + 8, col,
                             fmaxf(acc[mt][nt][2] + bb0, 0.f),
                             fmaxf(acc[mt][nt][3] + bb1, 0.f));
        }
    }
    // copy w1 hi/lo + wB (plain, L2-resident)
    {
        uint4* dh = (uint4*)(smem + OFF_WH);
        uint4* dl = (uint4*)(smem + OFF_WL);
        const uint4* sh = (const uint4*)g_w1h;
        const uint4* sl = (const uint4*)g_w1l;
        #pragma unroll 4
        for (int i = tid; i < 2048; i += 256) { dh[i] = sh[i]; dl[i] = sl[i]; }
        float4* wb = (float4*)(smem + OFF_WB);
        const float4* ws = (const float4*)g_wBt;
        #pragma unroll 2
        for (int i = tid; i < 1024; i += 256) wb[i] = ws[i];
    }
    __syncthreads();

    // ---------- GEMM2: t1 = relu(h0 @ w1^T + b1) ----------
    zero_acc(acc);
    gemm_128(H0h, H0l, smem + OFF_WH, smem + OFF_WL, acc, mb, nb, g, tg);
    {
        __nv_bfloat16* T1h = (__nv_bfloat16*)(smem + OFF_T1H);
        __nv_bfloat16* T1l = (__nv_bfloat16*)(smem + OFF_T1L);
        #pragma unroll
        for (int mt = 0; mt < 2; ++mt) {
            const int m0 = mb + mt * 16 + g;
            #pragma unroll
            for (int nt = 0; nt < 4; ++nt) {
                const int col = nb + nt * 8 + 2 * tg;
                const float bb0 = __ldg(b1 + col), bb1 = __ldg(b1 + col + 1);
                store_split_pair(T1h, T1l, m0,     col,
                                 fmaxf(acc[mt][nt][0] + bb0, 0.f),
                                 fmaxf(acc[mt][nt][1] + bb1, 0.f));
                store_split_pair(T1h, T1l, m0 + 8, col,
                                 fmaxf(acc[mt][nt][2] + bb0, 0.f),
                                 fmaxf(acc[mt][nt][3] + bb1, 0.f));
            }
        }
    }
    __syncthreads();
    // copy w2 hi/lo over w1
    {
        uint4* dh = (uint4*)(smem + OFF_WH);
        uint4* dl = (uint4*)(smem + OFF_WL);
        const uint4* sh = (const uint4*)g_w2h;
        const uint4* sl = (const uint4*)g_w2l;
        #pragma unroll 4
        for (int i = tid; i < 2048; i += 256) { dh[i] = sh[i]; dl[i] = sl[i]; }
    }
    __syncthreads();

    // ---------- GEMM3: h1 = relu(h0 + t1 @ w2^T + b2) -> fp32 F1 ----------
    zero_acc(acc);
    gemm_128((__nv_bfloat16*)(smem + OFF_T1H), (__nv_bfloat16*)(smem + OFF_T1L),
             smem + OFF_WH, smem + OFF_WL, acc, mb, nb, g, tg);
    __syncthreads();   // all W reads done before F1 overlays W
    {
        float* F1 = (float*)(smem + OFF_F1);
        #pragma unroll
        for (int mt = 0; mt < 2; ++mt) {
            const int m0 = mb + mt * 16 + g;
            #pragma unroll
            for (int nt = 0; nt < 4; ++nt) {
                const int col = nb + nt * 8 + 2 * tg;
                const float bb0 = __ldg(b2 + col), bb1 = __ldg(b2 + col + 1);
                const float h00 = __bfloat162float(H0h[m0 * S2ST + col])
                                + __bfloat162float(H0l[m0 * S2ST + col]);
                const float h01 = __bfloat162float(H0h[m0 * S2ST + col + 1])
                                + __bfloat162float(H0l[m0 * S2ST + col + 1]);
                const float h10 = __bfloat162float(H0h[(m0 + 8) * S2ST + col])
                                + __bfloat162float(H0l[(m0 + 8) * S2ST + col]);
                const float h11 = __bfloat162float(H0h[(m0 + 8) * S2ST + col + 1])
                                + __bfloat162float(H0l[(m0 + 8) * S2ST + col + 1]);
                F1[m0 * F1ST + col]           = fmaxf(h00 + acc[mt][nt][0] + bb0, 0.f);
                F1[m0 * F1ST + col + 1]       = fmaxf(h01 + acc[mt][nt][1] + bb1, 0.f);
                F1[(m0 + 8) * F1ST + col]     = fmaxf(h10 + acc[mt][nt][2] + bb0, 0.f);
                F1[(m0 + 8) * F1ST + col + 1] = fmaxf(h11 + acc[mt][nt][3] + bb1, 0.f);
            }
        }
    }
    __syncthreads();

    // ---------- Stage 3: h2 = relu(h1 @ wB^T + bB) ----------
    {
        const float* F1 = (const float*)(smem + OFF_F1);
        const float* wBs = (const float*)(smem + OFF_WB);
        float* F2 = (float*)(smem + OFF_F2);
        const int r  = tid >> 2;
        const int n0 = (tid & 3) * 8;
        float a3[8];
        #pragma unroll
        for (int i = 0; i < 8; ++i) a3[i] = 0.f;
        #pragma unroll 4
        for (int k = 0; k < 128; ++k) {
            const float hv = F1[r * F1ST + k];
            const float4 q0 = *(const float4*)(wBs + k * 32 + n0);
            const float4 q1 = *(const float4*)(wBs + k * 32 + n0 + 4);
            a3[0] = fmaf(hv, q0.x, a3[0]); a3[1] = fmaf(hv, q0.y, a3[1]);
            a3[2] = fmaf(hv, q0.z, a3[2]); a3[3] = fmaf(hv, q0.w, a3[3]);
            a3[4] = fmaf(hv, q1.x, a3[4]); a3[5] = fmaf(hv, q1.y, a3[5]);
            a3[6] = fmaf(hv, q1.z, a3[6]); a3[7] = fmaf(hv, q1.w, a3[7]);
        }
        #pragma unroll
        for (int n = 0; n < 8; ++n)
            F2[r * 36 + n0 + n] = fmaxf(a3[n] + __ldg(bB + n0 + n), 0.f);
    }
    __syncthreads();

    // ---------- Stage 4: logits ----------
    if (tid < 128) {
        const float* F2 = (const float*)(smem + OFF_F2);
        const int r = tid >> 1, c = tid & 1;
        float s = __ldg(bC + c);
        #pragma unroll
        for (int k = 0; k < 32; ++k)
            s = fmaf(F2[r * 36 + k], __ldg(wC + c * 32 + k), s);
        out[(size_t)(row0 + r) * 2 + c] = s;
    }
}

// ---------------- launch ----------------
extern "C" void kernel_launch(void* const* d_in, const int* in_sizes, int n_in,
                              void* d_out, int out_size)
{
    const float* x      = (const float*)d_in[0];
    const float* w_step = (const float*)d_in[1];
    const float* b_step = (const float*)d_in[2];
    const float* wA     = (const float*)d_in[3];
    const float* bA     = (const float*)d_in[4];
    const float* w1     = (const float*)d_in[5];
    const float* b1     = (const float*)d_in[6];
    const float* w2     = (const float*)d_in[7];
    const float* b2     = (const float*)d_in[8];
    const float* wB     = (const float*)d_in[9];
    const float* bB     = (const float*)d_in[10];
    const float* wC     = (const float*)d_in[11];
    const float* bC     = (const float*)d_in[12];
    float* out          = (float*)d_out;

    static bool attr_set = false;
    if (!attr_set) {
        cudaFuncSetAttribute(fused_kernel, cudaFuncAttributeMaxDynamicSharedMemorySize, SMEM_TOTAL);
        attr_set = true;
    }

    presplit_kernel<<<464, 256>>>(wA, w1, w2, wB);
    fused_kernel<<<NCTA, 256, SMEM_TOTAL>>>(x, w_step, b_step, bA, b1, b2, bB, wC, bC, out);
}

// round 7
// speedup vs baseline: 1.4885x; 1.4881x over previous
#include <cuda_runtime.h>
#include <cuda_bf16.h>
#include <stdint.h>

// ---------------- problem constants ----------------
#define BATCH   16384
#define QS      1204
#define FD      7
#define ROWLEN  (QS*FD)            // 8428 floats
#define ROW4    (ROWLEN/4)         // 2107
#define RPC     64                 // rows per MLP CTA
#define NCTA    (BATCH/RPC)        // 256
#define FK      600
#define FKP     640
#define NCH1    20                 // k-chunks of 32 in GEMM1
#define AROWB   1280               // bytes per feat row (640 * 2)
#define S2ST    136                // stage-2 A-side stride (bf16 elems)
#define F1ST    133                // fp32 h1 stride

// ---------------- mlp smem layout (bytes) ----------------
#define OFF_AH   0                 // 64*1280 = 81920
#define OFF_AL   81920             // 81920           -> ends 163840
#define OFF_B0   163840            // 2 x 16384 ring  -> ends 196608
#define SMEM_TOTAL 196608
// stage-2+ overlays (A region dead after GEMM1):
#define OFF_H0H  0
#define OFF_H0L  17408
#define OFF_WH   34816             // 4*4096*2 = 32768
#define OFF_WL   67584
#define OFF_T1H  100352
#define OFF_T1L  117760            // ends 135168
#define OFF_F1   34816             // fp32 64*133*4 = 34048 (overlays W after gemm3)
// ring region overlays:
#define OFF_WB   163840            // 128*32*4 = 16384 fp32
#define OFF_F2   180224            // 64*36*4  = 9216

// ---------------- global scratch ----------------
__device__ __align__(16) __nv_bfloat16 g_feat_hi[(size_t)BATCH*FKP];
__device__ __align__(16) __nv_bfloat16 g_feat_lo[(size_t)BATCH*FKP];
__device__ __align__(16) __nv_bfloat16 g_wAh[NCH1*4096];
__device__ __align__(16) __nv_bfloat16 g_wAl[NCH1*4096];
__device__ __align__(16) __nv_bfloat16 g_w1h[4*4096];
__device__ __align__(16) __nv_bfloat16 g_w1l[4*4096];
__device__ __align__(16) __nv_bfloat16 g_w2h[4*4096];
__device__ __align__(16) __nv_bfloat16 g_w2l[4*4096];
__device__ __align__(16) float         g_wBt[128*32];

// ---------------- helpers ----------------
__device__ __forceinline__ void split_bf16(float v, __nv_bfloat16& hi, __nv_bfloat16& lo) {
    hi = __float2bfloat16(v);
    lo = __float2bfloat16(v - __bfloat162float(hi));
}
__device__ __forceinline__ uint32_t pack_bf2(__nv_bfloat16 e0, __nv_bfloat16 e1) {
    return ((uint32_t)__bfloat16_as_ushort(e1) << 16) | (uint32_t)__bfloat16_as_ushort(e0);
}
__device__ __forceinline__ uint32_t smem_u32(const void* p) {
    return (uint32_t)__cvta_generic_to_shared(p);
}
__device__ __forceinline__ void mbar_init(uint32_t mbar, uint32_t cnt) {
    asm volatile("mbarrier.init.shared.b64 [%0], %1;" :: "r"(mbar), "r"(cnt) : "memory");
}
__device__ __forceinline__ void mbar_expect_tx(uint32_t mbar, uint32_t bytes) {
    asm volatile("mbarrier.arrive.expect_tx.shared.b64 _, [%0], %1;" :: "r"(mbar), "r"(bytes) : "memory");
}
__device__ __forceinline__ void mbar_wait(uint32_t mbar, uint32_t parity) {
    asm volatile(
        "{\n\t.reg .pred P;\n"
        "W%=:\n\t"
        "mbarrier.try_wait.parity.acquire.cta.shared::cta.b64 P, [%0], %1, 0x989680;\n\t"
        "@P bra D%=;\n\t"
        "bra W%=;\n"
        "D%=:\n\t}"
        :: "r"(mbar), "r"(parity) : "memory");
}
__device__ __forceinline__ void bulk_in(uint32_t dst, const void* src, uint32_t bytes, uint32_t mbar) {
    asm volatile(
        "cp.async.bulk.shared::cta.global.mbarrier::complete_tx::bytes [%0], [%1], %2, [%3];"
        :: "r"(dst), "l"(src), "r"(bytes), "r"(mbar) : "memory");
}
__device__ __forceinline__ void mma16816(float* c,
    uint32_t a0, uint32_t a1, uint32_t a2, uint32_t a3, uint32_t b0, uint32_t b1)
{
    asm volatile(
        "mma.sync.aligned.m16n8k16.row.col.f32.bf16.bf16.f32 "
        "{%0,%1,%2,%3}, {%4,%5,%6,%7}, {%8,%9}, {%0,%1,%2,%3};\n"
        : "+f"(c[0]), "+f"(c[1]), "+f"(c[2]), "+f"(c[3])
        : "r"(a0), "r"(a1), "r"(a2), "r"(a3), "r"(b0), "r"(b1));
}
// B tiles: rows of 64B, byte-in-row rotated by 8*(n&7)
__device__ __forceinline__ uint32_t ldsB(const char* base, int n, int kloc) {
    const int byte = n * 64 + ((2 * kloc + 8 * (n & 7)) & 63);
    return *(const uint32_t*)(base + byte);
}
// A tiles: row stride 1280B, XOR swizzle by ((r&7)<<4); kByte must be 4-aligned
__device__ __forceinline__ uint32_t ldsA(const char* base, int r, int kByte) {
    const int off = r * AROWB + (kByte ^ ((r & 7) << 4));
    return *(const uint32_t*)(base + off);
}

// ---------------- kernel 1: x -> feat (hi/lo bf16, swizzled rows) ----------------
__global__ __launch_bounds__(256) void feat_kernel(
    const float* __restrict__ x,
    const float* __restrict__ w_step,
    const float* __restrict__ b_step)
{
    __shared__ float sx[ROWLEN];
    __shared__ float ss[QS];

    const int row = blockIdx.x;
    const int tid = threadIdx.x;

    const float4* src = (const float4*)(x + (size_t)row * ROWLEN);
    float4* dst = (float4*)sx;
    #pragma unroll 4
    for (int i = tid; i < ROW4; i += 256) dst[i] = src[i];

    const float w0 = __ldg(w_step + 0), w1 = __ldg(w_step + 1), w2 = __ldg(w_step + 2),
                w3 = __ldg(w_step + 3), w4 = __ldg(w_step + 4), w5 = __ldg(w_step + 5),
                w6 = __ldg(w_step + 6), bs = __ldg(b_step);
    __syncthreads();

    for (int q = tid; q < QS; q += 256) {
        const float* p = sx + q * FD;
        float v = fmaf(p[0], w0, fmaf(p[1], w1, fmaf(p[2], w2,
                  fmaf(p[3], w3, fmaf(p[4], w4, fmaf(p[5], w5, p[6] * w6))))));
        ss[q] = v + bs;
    }
    __syncthreads();

    char* fh = (char*)g_feat_hi + (size_t)row * AROWB;
    char* fl = (char*)g_feat_lo + (size_t)row * AROWB;
    const int key = (row & 7) << 4;

    for (int t = tid; t < FKP / 2; t += 256) {
        const int j0 = 2 * t;
        float v0 = 0.f, v1 = 0.f;
        if (j0 < FK) {
            {
                const int bl = j0 / 5, off = j0 % 5;
                const float* p = ss + off + bl * 10;
                float m = p[0];
                #pragma unroll
                for (int i = 1; i < 10; ++i) m = fmaxf(m, p[i]);
                v0 = m;
            }
            {
                const int j1 = j0 + 1;
                const int bl = j1 / 5, off = j1 % 5;
                const float* p = ss + off + bl * 10;
                float m = p[0];
                #pragma unroll
                for (int i = 1; i < 10; ++i) m = fmaxf(m, p[i]);
                v1 = m;
            }
        }
        __nv_bfloat16 h0, l0, h1, l1;
        split_bf16(v0, h0, l0);
        split_bf16(v1, h1, l1);
        const int off = (4 * t) ^ key;
        *(uint32_t*)(fh + off) = pack_bf2(h0, h1);
        *(uint32_t*)(fl + off) = pack_bf2(l0, l1);
    }
}

// ---------------- pre-split kernel ----------------
__global__ __launch_bounds__(256) void presplit_kernel(
    const float* __restrict__ wA, const float* __restrict__ w1,
    const float* __restrict__ w2, const float* __restrict__ wB)
{
    int id = blockIdx.x * 256 + threadIdx.x;
    if (id < 81920) {
        const int n = id / FKP, k = id % FKP;
        const float v = (k < FK) ? __ldg(wA + n * FK + k) : 0.f;
        __nv_bfloat16 h, l; split_bf16(v, h, l);
        const int idx = (k >> 5) * 4096 + n * 32 + (((2 * (k & 31) + 8 * (n & 7)) & 63) >> 1);
        g_wAh[idx] = h; g_wAl[idx] = l;
    } else if (id < 98304) {
        const int t = id - 81920, n = t >> 7, k = t & 127;
        __nv_bfloat16 h, l; split_bf16(__ldg(w1 + n * 128 + k), h, l);
        const int idx = (k >> 5) * 4096 + n * 32 + (((2 * (k & 31) + 8 * (n & 7)) & 63) >> 1);
        g_w1h[idx] = h; g_w1l[idx] = l;
    } else if (id < 114688) {
        const int t = id - 98304, n = t >> 7, k = t & 127;
        __nv_bfloat16 h, l; split_bf16(__ldg(w2 + n * 128 + k), h, l);
        const int idx = (k >> 5) * 4096 + n * 32 + (((2 * (k & 31) + 8 * (n & 7)) & 63) >> 1);
        g_w2h[idx] = h; g_w2l[idx] = l;
    } else if (id < 118784) {
        const int t = id - 114688, k = t >> 5, n = t & 31;
        g_wBt[k * 32 + n] = __ldg(wB + n * 128 + k);
    }
}

// ---------------- GEMM inner helpers ----------------
// GEMM1: A swizzled stride-1280B rows, one 32-wide k-chunk of B
__device__ __forceinline__ void gemm_chunk_Aswz(
    const char* Ah, const char* Al,
    const char* Bh, const char* Bl,
    int kbase, float (&acc)[2][4][4], int mb, int nb, int g, int tg)
{
    #pragma unroll
    for (int kk = 0; kk < 2; ++kk) {
        const int kloc = kk * 16 + 2 * tg;
        const int kB = 2 * (kbase + kloc);
        uint32_t ah[2][4], al[2][4];
        #pragma unroll
        for (int mt = 0; mt < 2; ++mt) {
            const int r = mb + mt * 16 + g;
            ah[mt][0] = ldsA(Ah, r,     kB);
            ah[mt][1] = ldsA(Ah, r + 8, kB);
            ah[mt][2] = ldsA(Ah, r,     kB + 16);
            ah[mt][3] = ldsA(Ah, r + 8, kB + 16);
            al[mt][0] = ldsA(Al, r,     kB);
            al[mt][1] = ldsA(Al, r + 8, kB);
            al[mt][2] = ldsA(Al, r,     kB + 16);
            al[mt][3] = ldsA(Al, r + 8, kB + 16);
        }
        #pragma unroll
        for (int nt = 0; nt < 4; ++nt) {
            const int n = nb + nt * 8 + g;
            const uint32_t bh0 = ldsB(Bh, n, kloc), bh1 = ldsB(Bh, n, kloc + 8);
            const uint32_t bl0 = ldsB(Bl, n, kloc), bl1 = ldsB(Bl, n, kloc + 8);
            #pragma unroll
            for (int mt = 0; mt < 2; ++mt) {
                mma16816(acc[mt][nt], ah[mt][0], ah[mt][1], ah[mt][2], ah[mt][3], bh0, bh1);
                mma16816(acc[mt][nt], ah[mt][0], ah[mt][1], ah[mt][2], ah[mt][3], bl0, bl1);
                mma16816(acc[mt][nt], al[mt][0], al[mt][1], al[mt][2], al[mt][3], bh0, bh1);
            }
        }
    }
}

// stage-2 GEMM: A stride 136 (H0/T1), B = 4 chunks of [128][32] swizzled, K=128
__device__ __forceinline__ void gemm_128(
    const __nv_bfloat16* Ah, const __nv_bfloat16* Al,
    const char* Bh, const char* Bl,
    float (&acc)[2][4][4], int mb, int nb, int g, int tg)
{
    #pragma unroll
    for (int kk = 0; kk < 8; ++kk) {
        const int k0 = kk * 16 + 2 * tg;
        const int ch = k0 >> 5, kloc = k0 & 31;
        const char* BhC = Bh + ch * 8192;
        const char* BlC = Bl + ch * 8192;
        uint32_t ah[2][4], al[2][4];
        #pragma unroll
        for (int mt = 0; mt < 2; ++mt) {
            const __nv_bfloat16* pa = Ah + (mb + mt * 16 + g) * S2ST + k0;
            ah[mt][0] = *(const uint32_t*)pa;
            ah[mt][1] = *(const uint32_t*)(pa + 8 * S2ST);
            ah[mt][2] = *(const uint32_t*)(pa + 8);
            ah[mt][3] = *(const uint32_t*)(pa + 8 * S2ST + 8);
            const __nv_bfloat16* pl = Al + (mb + mt * 16 + g) * S2ST + k0;
            al[mt][0] = *(const uint32_t*)pl;
            al[mt][1] = *(const uint32_t*)(pl + 8 * S2ST);
            al[mt][2] = *(const uint32_t*)(pl + 8);
            al[mt][3] = *(const uint32_t*)(pl + 8 * S2ST + 8);
        }
        #pragma unroll
        for (int nt = 0; nt < 4; ++nt) {
            const int n = nb + nt * 8 + g;
            const uint32_t bh0 = ldsB(BhC, n, kloc), bh1 = ldsB(BhC, n, kloc + 8);
            const uint32_t bl0 = ldsB(BlC, n, kloc), bl1 = ldsB(BlC, n, kloc + 8);
            #pragma unroll
            for (int mt = 0; mt < 2; ++mt) {
                mma16816(acc[mt][nt], ah[mt][0], ah[mt][1], ah[mt][2], ah[mt][3], bh0, bh1);
                mma16816(acc[mt][nt], ah[mt][0], ah[mt][1], ah[mt][2], ah[mt][3], bl0, bl1);
                mma16816(acc[mt][nt], al[mt][0], al[mt][1], al[mt][2], al[mt][3], bh0, bh1);
            }
        }
    }
}

__device__ __forceinline__ void zero_acc(float (&acc)[2][4][4]) {
    #pragma unroll
    for (int a = 0; a < 2; ++a)
        #pragma unroll
        for (int b = 0; b < 4; ++b)
            #pragma unroll
            for (int c = 0; c < 4; ++c) acc[a][b][c] = 0.f;
}

__device__ __forceinline__ void store_split_pair(
    __nv_bfloat16* H, __nv_bfloat16* L, int m, int col, float v0, float v1)
{
    __nv_bfloat16 h0, l0, h1, l1;
    split_bf16(v0, h0, l0);
    split_bf16(v1, h1, l1);
    *(uint32_t*)(H + m * S2ST + col) = pack_bf2(h0, h1);
    *(uint32_t*)(L + m * S2ST + col) = pack_bf2(l0, l1);
}

// ---------------- kernel 2: feat -> logits ----------------
__global__ __launch_bounds__(256, 1) void mlp_kernel(
    const float* __restrict__ bA,
    const float* __restrict__ b1, const float* __restrict__ b2,
    const float* __restrict__ bB,
    const float* __restrict__ wC, const float* __restrict__ bC,
    float* __restrict__ out)
{
    extern __shared__ __align__(16) char smem[];
    __shared__ __align__(8) unsigned long long mb_a;
    __shared__ __align__(8) unsigned long long mb_b[2];

    const int tid  = threadIdx.x;
    const int wid  = tid >> 5;
    const int lane = tid & 31;
    const int g    = lane >> 2;
    const int tg   = lane & 3;
    const int mb   = (wid & 1) * 32;
    const int nb   = (wid >> 1) * 32;
    const int row0 = blockIdx.x * RPC;

    if (tid == 0) {
        mbar_init(smem_u32(&mb_a), 1);
        mbar_init(smem_u32(&mb_b[0]), 1);
        mbar_init(smem_u32(&mb_b[1]), 1);
    }
    __syncthreads();

    // issue A copies (feat hi/lo, 8 x 20480B) + first two B chunks
    if (tid == 0) {
        const uint32_t ma = smem_u32(&mb_a);
        mbar_expect_tx(ma, 2 * RPC * AROWB);
        const char* fh = (const char*)g_feat_hi + (size_t)row0 * AROWB;
        const char* fl = (const char*)g_feat_lo + (size_t)row0 * AROWB;
        #pragma unroll
        for (int i = 0; i < 4; ++i) {
            bulk_in(smem_u32(smem + OFF_AH) + i * 20480, fh + i * 20480, 20480, ma);
            bulk_in(smem_u32(smem + OFF_AL) + i * 20480, fl + i * 20480, 20480, ma);
        }
        #pragma unroll
        for (int c = 0; c < 2; ++c) {
            const uint32_t m = smem_u32(&mb_b[c]);
            mbar_expect_tx(m, 16384);
            bulk_in(smem_u32(smem + OFF_B0) + c * 16384,        (const char*)g_wAh + c * 8192, 8192, m);
            bulk_in(smem_u32(smem + OFF_B0) + c * 16384 + 8192, (const char*)g_wAl + c * 8192, 8192, m);
        }
    }

    // ---------- GEMM1: h0 = relu(feat @ wA^T + bA) ----------
    float acc[2][4][4];
    zero_acc(acc);
    mbar_wait(smem_u32(&mb_a), 0);
    for (int c = 0; c < NCH1; ++c) {
        const int buf = c & 1;
        mbar_wait(smem_u32(&mb_b[buf]), (c >> 1) & 1);
        gemm_chunk_Aswz(smem + OFF_AH, smem + OFF_AL,
                        smem + OFF_B0 + buf * 16384,
                        smem + OFF_B0 + buf * 16384 + 8192,
                        c * 32, acc, mb, nb, g, tg);
        __syncthreads();
        if (tid == 0 && c + 2 < NCH1) {
            const int nc = c + 2;
            const uint32_t m = smem_u32(&mb_b[buf]);
            mbar_expect_tx(m, 16384);
            bulk_in(smem_u32(smem + OFF_B0) + buf * 16384,        (const char*)g_wAh + nc * 8192, 8192, m);
            bulk_in(smem_u32(smem + OFF_B0) + buf * 16384 + 8192, (const char*)g_wAl + nc * 8192, 8192, m);
        }
    }

    // epilogue 1: h0 -> split bf16 H0 (A region dead after loop's final syncthreads)
    __nv_bfloat16* H0h = (__nv_bfloat16*)(smem + OFF_H0H);
    __nv_bfloat16* H0l = (__nv_bfloat16*)(smem + OFF_H0L);
    #pragma unroll
    for (int mt = 0; mt < 2; ++mt) {
        const int m0 = mb + mt * 16 + g;
        #pragma unroll
        for (int nt = 0; nt < 4; ++nt) {
            const int col = nb + nt * 8 + 2 * tg;
            const float bb0 = __ldg(bA + col), bb1 = __ldg(bA + col + 1);
            store_split_pair(H0h, H0l, m0,     col,
                             fmaxf(acc[mt][nt][0] + bb0, 0.f),
                             fmaxf(acc[mt][nt][1] + bb1, 0.f));
            store_split_pair(H0h, H0l, m0 + 8, col,
                             fmaxf(acc[mt][nt][2] + bb0, 0.f),
                             fmaxf(acc[mt][nt][3] + bb1, 0.f));
        }
    }
    // copy w1 hi/lo + wB (L2-resident); ring region dead
    {
        uint4* dh = (uint4*)(smem + OFF_WH);
        uint4* dl = (uint4*)(smem + OFF_WL);
        const uint4* sh = (const uint4*)g_w1h;
        const uint4* sl = (const uint4*)g_w1l;
        #pragma unroll 4
        for (int i = tid; i < 2048; i += 256) { dh[i] = sh[i]; dl[i] = sl[i]; }
        float4* wb = (float4*)(smem + OFF_WB);
        const float4* ws = (const float4*)g_wBt;
        #pragma unroll 2
        for (int i = tid; i < 1024; i += 256) wb[i] = ws[i];
    }
    __syncthreads();

    // ---------- GEMM2: t1 = relu(h0 @ w1^T + b1) ----------
    zero_acc(acc);
    gemm_128(H0h, H0l, smem + OFF_WH, smem + OFF_WL, acc, mb, nb, g, tg);
    {
        __nv_bfloat16* T1h = (__nv_bfloat16*)(smem + OFF_T1H);
        __nv_bfloat16* T1l = (__nv_bfloat16*)(smem + OFF_T1L);
        #pragma unroll
        for (int mt = 0; mt < 2; ++mt) {
            const int m0 = mb + mt * 16 + g;
            #pragma unroll
            for (int nt = 0; nt < 4; ++nt) {
                const int col = nb + nt * 8 + 2 * tg;
                const float bb0 = __ldg(b1 + col), bb1 = __ldg(b1 + col + 1);
                store_split_pair(T1h, T1l, m0,     col,
                                 fmaxf(acc[mt][nt][0] + bb0, 0.f),
                                 fmaxf(acc[mt][nt][1] + bb1, 0.f));
                store_split_pair(T1h, T1l, m0 + 8, col,
                                 fmaxf(acc[mt][nt][2] + bb0, 0.f),
                                 fmaxf(acc[mt][nt][3] + bb1, 0.f));
            }
        }
    }
    __syncthreads();
    // copy w2 hi/lo over w1
    {
        uint4* dh = (uint4*)(smem + OFF_WH);
        uint4* dl = (uint4*)(smem + OFF_WL);
        const uint4* sh = (const uint4*)g_w2h;
        const uint4* sl = (const uint4*)g_w2l;
        #pragma unroll 4
        for (int i = tid; i < 2048; i += 256) { dh[i] = sh[i]; dl[i] = sl[i]; }
    }
    __syncthreads();

    // ---------- GEMM3: h1 = relu(h0 + t1 @ w2^T + b2) -> fp32 F1 ----------
    zero_acc(acc);
    gemm_128((__nv_bfloat16*)(smem + OFF_T1H), (__nv_bfloat16*)(smem + OFF_T1L),
             smem + OFF_WH, smem + OFF_WL, acc, mb, nb, g, tg);
    __syncthreads();   // all W reads done before F1 overlays W
    {
        float* F1 = (float*)(smem + OFF_F1);
        #pragma unroll
        for (int mt = 0; mt < 2; ++mt) {
            const int m0 = mb + mt * 16 + g;
            #pragma unroll
            for (int nt = 0; nt < 4; ++nt) {
                const int col = nb + nt * 8 + 2 * tg;
                const float bb0 = __ldg(b2 + col), bb1 = __ldg(b2 + col + 1);
                const float h00 = __bfloat162float(H0h[m0 * S2ST + col])
                                + __bfloat162float(H0l[m0 * S2ST + col]);
                const float h01 = __bfloat162float(H0h[m0 * S2ST + col + 1])
                                + __bfloat162float(H0l[m0 * S2ST + col + 1]);
                const float h10 = __bfloat162float(H0h[(m0 + 8) * S2ST + col])
                                + __bfloat162float(H0l[(m0 + 8) * S2ST + col]);
                const float h11 = __bfloat162float(H0h[(m0 + 8) * S2ST + col + 1])
                                + __bfloat162float(H0l[(m0 + 8) * S2ST + col + 1]);
                F1[m0 * F1ST + col]           = fmaxf(h00 + acc[mt][nt][0] + bb0, 0.f);
                F1[m0 * F1ST + col + 1]       = fmaxf(h01 + acc[mt][nt][1] + bb1, 0.f);
                F1[(m0 + 8) * F1ST + col]     = fmaxf(h10 + acc[mt][nt][2] + bb0, 0.f);
                F1[(m0 + 8) * F1ST + col + 1] = fmaxf(h11 + acc[mt][nt][3] + bb1, 0.f);
            }
        }
    }
    __syncthreads();

    // ---------- Stage 3: h2 = relu(h1 @ wB^T + bB) ----------
    {
        const float* F1 = (const float*)(smem + OFF_F1);
        const float* wBs = (const float*)(smem + OFF_WB);
        float* F2 = (float*)(smem + OFF_F2);
        const int r  = tid >> 2;
        const int n0 = (tid & 3) * 8;
        float a3[8];
        #pragma unroll
        for (int i = 0; i < 8; ++i) a3[i] = 0.f;
        #pragma unroll 4
        for (int k = 0; k < 128; ++k) {
            const float hv = F1[r * F1ST + k];
            const float4 q0 = *(const float4*)(wBs + k * 32 + n0);
            const float4 q1 = *(const float4*)(wBs + k * 32 + n0 + 4);
            a3[0] = fmaf(hv, q0.x, a3[0]); a3[1] = fmaf(hv, q0.y, a3[1]);
            a3[2] = fmaf(hv, q0.z, a3[2]); a3[3] = fmaf(hv, q0.w, a3[3]);
            a3[4] = fmaf(hv, q1.x, a3[4]); a3[5] = fmaf(hv, q1.y, a3[5]);
            a3[6] = fmaf(hv, q1.z, a3[6]); a3[7] = fmaf(hv, q1.w, a3[7]);
        }
        #pragma unroll
        for (int n = 0; n < 8; ++n)
            F2[r * 36 + n0 + n] = fmaxf(a3[n] + __ldg(bB + n0 + n), 0.f);
    }
    __syncthreads();

    // ---------- Stage 4: logits ----------
    if (tid < 128) {
        const float* F2 = (const float*)(smem + OFF_F2);
        const int r = tid >> 1, c = tid & 1;
        float s = __ldg(bC + c);
        #pragma unroll
        for (int k = 0; k < 32; ++k)
            s = fmaf(F2[r * 36 + k], __ldg(wC + c * 32 + k), s);
        out[(size_t)(row0 + r) * 2 + c] = s;
    }
}

// ---------------- launch ----------------
extern "C" void kernel_launch(void* const* d_in, const int* in_sizes, int n_in,
                              void* d_out, int out_size)
{
    const float* x      = (const float*)d_in[0];
    const float* w_step = (const float*)d_in[1];
    const float* b_step = (const float*)d_in[2];
    const float* wA     = (const float*)d_in[3];
    const float* bA     = (const float*)d_in[4];
    const float* w1     = (const float*)d_in[5];
    const float* b1     = (const float*)d_in[6];
    const float* w2     = (const float*)d_in[7];
    const float* b2     = (const float*)d_in[8];
    const float* wB     = (const float*)d_in[9];
    const float* bB     = (const float*)d_in[10];
    const float* wC     = (const float*)d_in[11];
    const float* bC     = (const float*)d_in[12];
    float* out          = (float*)d_out;

    static bool attr_set = false;
    if (!attr_set) {
        cudaFuncSetAttribute(mlp_kernel, cudaFuncAttributeMaxDynamicSharedMemorySize, SMEM_TOTAL);
        attr_set = true;
    }

    presplit_kernel<<<464, 256>>>(wA, w1, w2, wB);
    feat_kernel<<<BATCH, 256>>>(x, w_step, b_step);
    mlp_kernel<<<NCTA, 256, SMEM_TOTAL>>>(bA, b1, b2, bB, wC, bC, out);
}

// round 12
// speedup vs baseline: 1.5979x; 1.0736x over previous
#include <cuda_runtime.h>
#include <cuda_bf16.h>
#include <stdint.h>

// ---------------- problem constants ----------------
#define BATCH   16384
#define QS      1204
#define FD      7
#define ROWLEN  (QS*FD)            // 8428 floats
#define ROW4    (ROWLEN/4)         // 2107
#define FK      600
#define RPC     64                 // rows per MLP CTA
#define NCTA    (BATCH/RPC)        // 256
#define NCH     20                 // 32-wide k-chunks in GEMM1 (640 = 20*32)
#define NCHT    28                 // + 4 w1 + 4 w2 chunks streamed after

// per-(blk,chunk) feat block: [Ahi 4KB | Alo 4KB]
#define ACHB    8192
#define FBLKB   (NCH*ACHB)         // 163840 per row-block
// per weight chunk block: [Bhi 8KB | Blo 8KB]
#define WCHB    16384

// ---------------- mlp smem layout (bytes) ----------------
// ring: 2 slots x 24KB; slot = [Ahi 4K|Alo 4K|Bhi 8K|Blo 8K]
#define SLOTB    24576
#define OFF_RING 0                 // 49152
#define OFF_H0   49152             // [hi 16K|lo 16K] 64 rows x 256B, XOR swz
#define OFF_T1   81920             // same, 32KB
#define SMEM_TOTAL 114688
// overlays (after GEMM3):
#define OFF_F1   0                 // fp32 64x133 = 34048 (over ring)
#define OFF_WB   OFF_H0            // fp32 128x32 = 16384 (over H0, post-residual)
#define OFF_F2   OFF_T1            // fp32 64x36  = 9216  (over T1)
#define F1ST     133

// ---------------- global scratch ----------------
__device__ __align__(128) char g_fA [(size_t)NCTA*FBLKB];  // 40MB feat tiles
__device__ __align__(128) char g_wAt[NCH*WCHB];            // wA chunk tiles
__device__ __align__(128) char g_w1t[4*WCHB];
__device__ __align__(128) char g_w2t[4*WCHB];

// ---------------- helpers ----------------
__device__ __forceinline__ void split_bf16(float v, __nv_bfloat16& hi, __nv_bfloat16& lo) {
    hi = __float2bfloat16(v);
    lo = __float2bfloat16(v - __bfloat162float(hi));
}
__device__ __forceinline__ uint32_t pack_bf2(__nv_bfloat16 e0, __nv_bfloat16 e1) {
    return ((uint32_t)__bfloat16_as_ushort(e1) << 16) | (uint32_t)__bfloat16_as_ushort(e0);
}
__device__ __forceinline__ uint32_t smem_u32(const void* p) {
    return (uint32_t)__cvta_generic_to_shared(p);
}
__device__ __forceinline__ void mbar_init(uint32_t mbar, uint32_t cnt) {
    asm volatile("mbarrier.init.shared.b64 [%0], %1;" :: "r"(mbar), "r"(cnt) : "memory");
}
__device__ __forceinline__ void mbar_expect_tx(uint32_t mbar, uint32_t bytes) {
    asm volatile("mbarrier.arrive.expect_tx.shared.b64 _, [%0], %1;" :: "r"(mbar), "r"(bytes) : "memory");
}
__device__ __forceinline__ void mbar_wait(uint32_t mbar, uint32_t parity) {
    asm volatile(
        "{\n\t.reg .pred P;\n"
        "W%=:\n\t"
        "mbarrier.try_wait.parity.acquire.cta.shared::cta.b64 P, [%0], %1, 0x989680;\n\t"
        "@P bra D%=;\n\t"
        "bra W%=;\n"
        "D%=:\n\t}"
        :: "r"(mbar), "r"(parity) : "memory");
}
__device__ __forceinline__ void bulk_in(uint32_t dst, const void* src, uint32_t bytes, uint32_t mbar) {
    asm volatile(
        "cp.async.bulk.shared::cta.global.mbarrier::complete_tx::bytes [%0], [%1], %2, [%3];"
        :: "r"(dst), "l"(src), "r"(bytes), "r"(mbar) : "memory");
}
__device__ __forceinline__ void mma16816(float* c,
    uint32_t a0, uint32_t a1, uint32_t a2, uint32_t a3, uint32_t b0, uint32_t b1)
{
    asm volatile(
        "mma.sync.aligned.m16n8k16.row.col.f32.bf16.bf16.f32 "
        "{%0,%1,%2,%3}, {%4,%5,%6,%7}, {%8,%9}, {%0,%1,%2,%3};\n"
        : "+f"(c[0]), "+f"(c[1]), "+f"(c[2]), "+f"(c[3])
        : "r"(a0), "r"(a1), "r"(a2), "r"(a3), "r"(b0), "r"(b1));
}
// B tiles: 64B rows, byte-in-row rotated by 8*(n&7)
__device__ __forceinline__ uint32_t ldB(const char* base, int n, int kloc) {
    return *(const uint32_t*)(base + n * 64 + ((2 * kloc + 8 * (n & 7)) & 63));
}
// A chunk tiles: 64B rows, XOR key (r&3)<<4
__device__ __forceinline__ uint32_t ldA(const char* base, int r, int kB) {
    return *(const uint32_t*)(base + r * 64 + (kB ^ ((r & 3) << 4)));
}
// H/T tiles: 256B rows, XOR key (r&7)<<4
__device__ __forceinline__ uint32_t ldH(const char* base, int r, int kB) {
    return *(const uint32_t*)(base + r * 256 + (kB ^ ((r & 7) << 4)));
}
__device__ __forceinline__ void zero_acc(float (&acc)[2][4][4]) {
    #pragma unroll
    for (int a = 0; a < 2; ++a)
        #pragma unroll
        for (int b = 0; b < 4; ++b)
            #pragma unroll
            for (int c = 0; c < 4; ++c) acc[a][b][c] = 0.f;
}
// store split pair into a 256B-row tile (hi plane at base, lo at +16KB)
__device__ __forceinline__ void storeTile(char* base, int r, int col, float v0, float v1) {
    __nv_bfloat16 h0, l0, h1, l1;
    split_bf16(v0, h0, l0); split_bf16(v1, h1, l1);
    const int off = r * 256 + ((2 * col) ^ ((r & 7) << 4));
    *(uint32_t*)(base + off)         = pack_bf2(h0, h1);
    *(uint32_t*)(base + off + 16384) = pack_bf2(l0, l1);
}

// GEMM1 chunk (A 64B-row chunk tile, B 32-wide chunk)
__device__ __forceinline__ void gemm1_chunk(const char* slot,
    float (&acc)[2][4][4], int mb, int nb, int g, int tg)
{
    const char* Ah = slot;
    const char* Al = slot + 4096;
    const char* Bh = slot + 8192;
    const char* Bl = slot + 16384;
    #pragma unroll
    for (int kk = 0; kk < 2; ++kk) {
        const int kloc = kk * 16 + 2 * tg;
        const int kB = 2 * kloc;
        uint32_t ah[2][4], al[2][4];
        #pragma unroll
        for (int mt = 0; mt < 2; ++mt) {
            const int r = mb + mt * 16 + g;
            ah[mt][0] = ldA(Ah, r,     kB);
            ah[mt][1] = ldA(Ah, r + 8, kB);
            ah[mt][2] = ldA(Ah, r,     kB + 16);
            ah[mt][3] = ldA(Ah, r + 8, kB + 16);
            al[mt][0] = ldA(Al, r,     kB);
            al[mt][1] = ldA(Al, r + 8, kB);
            al[mt][2] = ldA(Al, r,     kB + 16);
            al[mt][3] = ldA(Al, r + 8, kB + 16);
        }
        #pragma unroll
        for (int nt = 0; nt < 4; ++nt) {
            const int n = nb + nt * 8 + g;
            const uint32_t bh0 = ldB(Bh, n, kloc), bh1 = ldB(Bh, n, kloc + 8);
            const uint32_t bl0 = ldB(Bl, n, kloc), bl1 = ldB(Bl, n, kloc + 8);
            #pragma unroll
            for (int mt = 0; mt < 2; ++mt) {
                mma16816(acc[mt][nt], ah[mt][0], ah[mt][1], ah[mt][2], ah[mt][3], bh0, bh1);
                mma16816(acc[mt][nt], ah[mt][0], ah[mt][1], ah[mt][2], ah[mt][3], bl0, bl1);
                mma16816(acc[mt][nt], al[mt][0], al[mt][1], al[mt][2], al[mt][3], bh0, bh1);
            }
        }
    }
}

// GEMM2/3 chunk (A = H0/T1 256B-row tile at kbase, B chunk in ring slot)
__device__ __forceinline__ void gemm23_chunk(const char* Abase, const char* slot,
    int kbase, float (&acc)[2][4][4], int mb, int nb, int g, int tg)
{
    const char* Ah = Abase;
    const char* Al = Abase + 16384;
    const char* Bh = slot + 8192;
    const char* Bl = slot + 16384;
    #pragma unroll
    for (int kk = 0; kk < 2; ++kk) {
        const int kloc = kk * 16 + 2 * tg;
        const int kB = 2 * (kbase + kloc);
        uint32_t ah[2][4], al[2][4];
        #pragma unroll
        for (int mt = 0; mt < 2; ++mt) {
            const int r = mb + mt * 16 + g;
            ah[mt][0] = ldH(Ah, r,     kB);
            ah[mt][1] = ldH(Ah, r + 8, kB);
            ah[mt][2] = ldH(Ah, r,     kB + 16);
            ah[mt][3] = ldH(Ah, r + 8, kB + 16);
            al[mt][0] = ldH(Al, r,     kB);
            al[mt][1] = ldH(Al, r + 8, kB);
            al[mt][2] = ldH(Al, r,     kB + 16);
            al[mt][3] = ldH(Al, r + 8, kB + 16);
        }
        #pragma unroll
        for (int nt = 0; nt < 4; ++nt) {
            const int n = nb + nt * 8 + g;
            const uint32_t bh0 = ldB(Bh, n, kloc), bh1 = ldB(Bh, n, kloc + 8);
            const uint32_t bl0 = ldB(Bl, n, kloc), bl1 = ldB(Bl, n, kloc + 8);
            #pragma unroll
            for (int mt = 0; mt < 2; ++mt) {
                mma16816(acc[mt][nt], ah[mt][0], ah[mt][1], ah[mt][2], ah[mt][3], bh0, bh1);
                mma16816(acc[mt][nt], ah[mt][0], ah[mt][1], ah[mt][2], ah[mt][3], bl0, bl1);
                mma16816(acc[mt][nt], al[mt][0], al[mt][1], al[mt][2], al[mt][3], bh0, bh1);
            }
        }
    }
}

// ---------------- kernel 1: feat (+ merged presplit) ----------------
__global__ __launch_bounds__(256) void feat_presplit_kernel(
    const float* __restrict__ x,
    const float* __restrict__ w_step, const float* __restrict__ b_step,
    const float* __restrict__ wA, const float* __restrict__ w1,
    const float* __restrict__ w2)
{
    const int tid = threadIdx.x;

    if (blockIdx.x >= BATCH) {
        const int id = (blockIdx.x - BATCH) * 256 + tid;
        if (id < 81920) {                       // wA: 128 x 640 (zero-padded k>=600)
            const int n = id / 640, k = id % 640;
            const float v = (k < FK) ? __ldg(wA + n * FK + k) : 0.f;
            __nv_bfloat16 h, l; split_bf16(v, h, l);
            const int c = k >> 5, kl = k & 31;
            const int off = c * WCHB + n * 64 + ((2 * kl + 8 * (n & 7)) & 63);
            *(__nv_bfloat16*)(g_wAt + off)        = h;
            *(__nv_bfloat16*)(g_wAt + off + 8192) = l;
        } else if (id < 98304) {                // w1: 128 x 128
            const int t = id - 81920, n = t >> 7, k = t & 127;
            __nv_bfloat16 h, l; split_bf16(__ldg(w1 + n * 128 + k), h, l);
            const int c = k >> 5, kl = k & 31;
            const int off = c * WCHB + n * 64 + ((2 * kl + 8 * (n & 7)) & 63);
            *(__nv_bfloat16*)(g_w1t + off)        = h;
            *(__nv_bfloat16*)(g_w1t + off + 8192) = l;
        } else if (id < 114688) {               // w2
            const int t = id - 98304, n = t >> 7, k = t & 127;
            __nv_bfloat16 h, l; split_bf16(__ldg(w2 + n * 128 + k), h, l);
            const int c = k >> 5, kl = k & 31;
            const int off = c * WCHB + n * 64 + ((2 * kl + 8 * (n & 7)) & 63);
            *(__nv_bfloat16*)(g_w2t + off)        = h;
            *(__nv_bfloat16*)(g_w2t + off + 8192) = l;
        }
        return;
    }

    // ---- feat: one block per batch row ----
    __shared__ float sx[ROWLEN];
    __shared__ float ss[QS];

    const int row = blockIdx.x;
    const float4* src = (const float4*)(x + (size_t)row * ROWLEN);
    float4* dst = (float4*)sx;
    #pragma unroll 4
    for (int i = tid; i < ROW4; i += 256) dst[i] = src[i];

    const float w0 = __ldg(w_step + 0), w1c = __ldg(w_step + 1), w2c = __ldg(w_step + 2),
                w3 = __ldg(w_step + 3), w4 = __ldg(w_step + 4), w5 = __ldg(w_step + 5),
                w6 = __ldg(w_step + 6), bs = __ldg(b_step);
    __syncthreads();

    for (int q = tid; q < QS; q += 256) {
        const float* p = sx + q * FD;
        float v = fmaf(p[0], w0, fmaf(p[1], w1c, fmaf(p[2], w2c,
                  fmaf(p[3], w3, fmaf(p[4], w4, fmaf(p[5], w5, p[6] * w6))))));
        ss[q] = v + bs;
    }
    __syncthreads();

    const int blk  = row >> 6;
    const int rloc = row & 63;
    char* fbase = g_fA + (size_t)blk * FBLKB;
    const int rbase = rloc * 64;
    const int key   = (rloc & 3) << 4;

    for (int t = tid; t < 320; t += 256) {       // 640/2 feature pairs
        const int j0 = 2 * t;
        float v0 = 0.f, v1 = 0.f;
        if (j0 < FK) {
            {
                const int bl = j0 / 5, off = j0 % 5;
                const float* p = ss + off + bl * 10;
                float m = p[0];
                #pragma unroll
                for (int i = 1; i < 10; ++i) m = fmaxf(m, p[i]);
                v0 = m;
            }
            {
                const int j1 = j0 + 1;
                const int bl = j1 / 5, off = j1 % 5;
                const float* p = ss + off + bl * 10;
                float m = p[0];
                #pragma unroll
                for (int i = 1; i < 10; ++i) m = fmaxf(m, p[i]);
                v1 = m;
            }
        }
        __nv_bfloat16 h0, l0, h1, l1;
        split_bf16(v0, h0, l0);
        split_bf16(v1, h1, l1);
        const int c = j0 >> 5, kl = j0 & 31;
        const int off = c * ACHB + rbase + ((2 * kl) ^ key);
        *(uint32_t*)(fbase + off)        = pack_bf2(h0, h1);
        *(uint32_t*)(fbase + off + 4096) = pack_bf2(l0, l1);
    }
}

// ---------------- kernel 2: MLP, streamed ring, 2 CTA/SM ----------------
__global__ __launch_bounds__(256, 2) void mlp_kernel(
    const float* __restrict__ bA, const float* __restrict__ b1,
    const float* __restrict__ b2, const float* __restrict__ bB,
    const float* __restrict__ wB, const float* __restrict__ wC,
    const float* __restrict__ bC, float* __restrict__ out)
{
    extern __shared__ __align__(16) char smem[];
    __shared__ __align__(8) unsigned long long s_mb[2];

    const int tid  = threadIdx.x;
    const int wid  = tid >> 5;
    const int lane = tid & 31;
    const int g    = lane >> 2;
    const int tg   = lane & 3;
    const int mb   = (wid & 1) * 32;
    const int nb   = (wid >> 1) * 32;
    const int row0 = blockIdx.x * RPC;
    const uint32_t smb = smem_u32(smem);

    if (tid == 0) {
        mbar_init(smem_u32(&s_mb[0]), 1);
        mbar_init(smem_u32(&s_mb[1]), 1);
    }
    __syncthreads();

    // fetch chunk cnt into ring slot cnt&1 (tid 0 only)
    auto fetch = [&](int cnt) {
        const int s = cnt & 1;
        const uint32_t m = smem_u32(&s_mb[s]);
        const uint32_t slot = smb + OFF_RING + s * SLOTB;
        if (cnt < NCH) {
            mbar_expect_tx(m, ACHB + WCHB);
            bulk_in(slot,        g_fA + (size_t)blockIdx.x * FBLKB + cnt * ACHB, ACHB, m);
            bulk_in(slot + 8192, g_wAt + cnt * WCHB,                             WCHB, m);
        } else if (cnt < 24) {
            mbar_expect_tx(m, WCHB);
            bulk_in(slot + 8192, g_w1t + (cnt - NCH) * WCHB, WCHB, m);
        } else {
            mbar_expect_tx(m, WCHB);
            bulk_in(slot + 8192, g_w2t + (cnt - 24) * WCHB, WCHB, m);
        }
    };

    if (tid == 0) { fetch(0); fetch(1); }

    float acc[2][4][4];

    // ---------- GEMM1: D1 = feat @ wA^T (20 chunks) ----------
    zero_acc(acc);
    for (int c = 0; c < NCH; ++c) {
        mbar_wait(smem_u32(&s_mb[c & 1]), (c >> 1) & 1);
        gemm1_chunk(smem + OFF_RING + (c & 1) * SLOTB, acc, mb, nb, g, tg);
        __syncthreads();
        if (tid == 0 && c + 2 < NCHT) fetch(c + 2);
    }

    // ---------- epilogue 1: H0 = relu(D1 + bA) split tiles ----------
    char* H0 = smem + OFF_H0;
    #pragma unroll
    for (int mt = 0; mt < 2; ++mt) {
        const int r0 = mb + mt * 16 + g;
        #pragma unroll
        for (int nt = 0; nt < 4; ++nt) {
            const int col = nb + nt * 8 + 2 * tg;
            const float bb0 = __ldg(bA + col), bb1 = __ldg(bA + col + 1);
            storeTile(H0, r0,     col, fmaxf(acc[mt][nt][0] + bb0, 0.f),
                                       fmaxf(acc[mt][nt][1] + bb1, 0.f));
            storeTile(H0, r0 + 8, col, fmaxf(acc[mt][nt][2] + bb0, 0.f),
                                       fmaxf(acc[mt][nt][3] + bb1, 0.f));
        }
    }
    __syncthreads();

    // ---------- GEMM2: D2 = h0 @ w1^T (chunks 20..23) ----------
    zero_acc(acc);
    for (int j = 0; j < 4; ++j) {
        const int cnt = NCH + j;
        mbar_wait(smem_u32(&s_mb[cnt & 1]), (cnt >> 1) & 1);
        gemm23_chunk(H0, smem + OFF_RING + (cnt & 1) * SLOTB, j * 32, acc, mb, nb, g, tg);
        __syncthreads();
        if (tid == 0 && cnt + 2 < NCHT) fetch(cnt + 2);
    }

    // ---------- epilogue 2: T1 = relu(D2 + b1) split tiles ----------
    char* T1 = smem + OFF_T1;
    #pragma unroll
    for (int mt = 0; mt < 2; ++mt) {
        const int r0 = mb + mt * 16 + g;
        #pragma unroll
        for (int nt = 0; nt < 4; ++nt) {
            const int col = nb + nt * 8 + 2 * tg;
            const float bb0 = __ldg(b1 + col), bb1 = __ldg(b1 + col + 1);
            storeTile(T1, r0,     col, fmaxf(acc[mt][nt][0] + bb0, 0.f),
                                       fmaxf(acc[mt][nt][1] + bb1, 0.f));
            storeTile(T1, r0 + 8, col, fmaxf(acc[mt][nt][2] + bb0, 0.f),
                                       fmaxf(acc[mt][nt][3] + bb1, 0.f));
        }
    }
    __syncthreads();

    // ---------- GEMM3: D3 = t1 @ w2^T (chunks 24..27) ----------
    zero_acc(acc);
    for (int j = 0; j < 4; ++j) {
        const int cnt = 24 + j;
        mbar_wait(smem_u32(&s_mb[cnt & 1]), (cnt >> 1) & 1);
        gemm23_chunk(T1, smem + OFF_RING + (cnt & 1) * SLOTB, j * 32, acc, mb, nb, g, tg);
        __syncthreads();
        if (tid == 0 && cnt + 2 < NCHT) fetch(cnt + 2);   // keep ring fed (chunks 26, 27)
    }

    // ---------- epilogue 3: F1 = relu(h0 + D3 + b2) fp32 (over ring) ----------
    {
        float* F1 = (float*)(smem + OFF_F1);
        #pragma unroll
        for (int mt = 0; mt < 2; ++mt) {
            #pragma unroll
            for (int nt = 0; nt < 4; ++nt) {
                const int col = nb + nt * 8 + 2 * tg;
                const float bb0 = __ldg(b2 + col), bb1 = __ldg(b2 + col + 1);
                #pragma unroll
                for (int half = 0; half < 2; ++half) {
                    const int r = mb + mt * 16 + g + half * 8;
                    const int off = r * 256 + ((2 * col) ^ ((r & 7) << 4));
                    const uint32_t ph = *(uint32_t*)(H0 + off);
                    const uint32_t pl = *(uint32_t*)(H0 + off + 16384);
                    const float h0v = __bfloat162float(__ushort_as_bfloat16((unsigned short)(ph & 0xFFFF)))
                                    + __bfloat162float(__ushort_as_bfloat16((unsigned short)(pl & 0xFFFF)));
                    const float h1v = __bfloat162float(__ushort_as_bfloat16((unsigned short)(ph >> 16)))
                                    + __bfloat162float(__ushort_as_bfloat16((unsigned short)(pl >> 16)));
                    const float a0 = acc[mt][nt][half * 2 + 0];
                    const float a1 = acc[mt][nt][half * 2 + 1];
                    F1[r * F1ST + col]     = fmaxf(h0v + a0 + bb0, 0.f);
                    F1[r * F1ST + col + 1] = fmaxf(h1v + a1 + bb1, 0.f);
                }
            }
        }
    }
    __syncthreads();

    // ---------- wB transpose copy (over H0, now dead) ----------
    {
        float* wBs = (float*)(smem + OFF_WB);
        #pragma unroll 4
        for (int i = tid; i < 4096; i += 256) {
            const int k = i >> 5, n = i & 31;
            wBs[i] = __ldg(wB + n * 128 + k);
        }
    }
    __syncthreads();

    // ---------- stage 3: h2 = relu(h1 @ wB^T + bB) scalar fp32 ----------
    {
        const float* F1 = (const float*)(smem + OFF_F1);
        const float* wBs = (const float*)(smem + OFF_WB);
        float* F2 = (float*)(smem + OFF_F2);
        const int r  = tid >> 2;
        const int n0 = (tid & 3) * 8;
        float a3[8];
        #pragma unroll
        for (int i = 0; i < 8; ++i) a3[i] = 0.f;
        #pragma unroll 4
        for (int k = 0; k < 128; ++k) {
            const float hv = F1[r * F1ST + k];
            const float4 q0 = *(const float4*)(wBs + k * 32 + n0);
            const float4 q1 = *(const float4*)(wBs + k * 32 + n0 + 4);
            a3[0] = fmaf(hv, q0.x, a3[0]); a3[1] = fmaf(hv, q0.y, a3[1]);
            a3[2] = fmaf(hv, q0.z, a3[2]); a3[3] = fmaf(hv, q0.w, a3[3]);
            a3[4] = fmaf(hv, q1.x, a3[4]); a3[5] = fmaf(hv, q1.y, a3[5]);
            a3[6] = fmaf(hv, q1.z, a3[6]); a3[7] = fmaf(hv, q1.w, a3[7]);
        }
        #pragma unroll
        for (int n = 0; n < 8; ++n)
            F2[r * 36 + n0 + n] = fmaxf(a3[n] + __ldg(bB + n0 + n), 0.f);
    }
    __syncthreads();

    // ---------- stage 4: logits ----------
    if (tid < 128) {
        const float* F2 = (const float*)(smem + OFF_F2);
        const int r = tid >> 1, c = tid & 1;
        float s = __ldg(bC + c);
        #pragma unroll
        for (int k = 0; k < 32; ++k)
            s = fmaf(F2[r * 36 + k], __ldg(wC + c * 32 + k), s);
        out[(size_t)(row0 + r) * 2 + c] = s;
    }
}

// ---------------- launch ----------------
extern "C" void kernel_launch(void* const* d_in, const int* in_sizes, int n_in,
                              void* d_out, int out_size)
{
    const float* x      = (const float*)d_in[0];
    const float* w_step = (const float*)d_in[1];
    const float* b_step = (const float*)d_in[2];
    const float* wA     = (const float*)d_in[3];
    const float* bA     = (const float*)d_in[4];
    const float* w1     = (const float*)d_in[5];
    const float* b1     = (const float*)d_in[6];
    const float* w2     = (const float*)d_in[7];
    const float* b2     = (const float*)d_in[8];
    const float* wB     = (const float*)d_in[9];
    const float* bB     = (const float*)d_in[10];
    const float* wC     = (const float*)d_in[11];
    const float* bC     = (const float*)d_in[12];
    float* out          = (float*)d_out;

    static bool attr_set = false;
    if (!attr_set) {
        cudaFuncSetAttribute(mlp_kernel, cudaFuncAttributeMaxDynamicSharedMemorySize, SMEM_TOTAL);
        attr_set = true;
    }

    feat_presplit_kernel<<<BATCH + 448, 256>>>(x, w_step, b_step, wA, w1, w2);
    mlp_kernel<<<NCTA, 256, SMEM_TOTAL>>>(bA, b1, b2, bB, wB, wC, bC, out);
}

// round 13
// speedup vs baseline: 1.8719x; 1.1714x over previous
#include <cuda_runtime.h>
#include <cuda_bf16.h>
#include <stdint.h>

// ---------------- problem constants ----------------
#define BATCH   16384
#define QS      1204
#define FD      7
#define ROWLEN  (QS*FD)            // 8428 floats
#define ROW4    (ROWLEN/4)         // 2107
#define FK      600
#define RPC     64                 // rows per MLP CTA
#define NCTA    (BATCH/RPC)        // 256
#define NCH     19                 // 32-wide k-chunks in GEMM1 (608 = 19*32, k>=600 zero)
#define NCHT    27                 // + 4 w1 + 4 w2 chunks streamed after
#define KP      608                // padded K for GEMM1

// per-(blk,chunk) feat block: [Ahi 4KB | Alo 4KB]
#define ACHB    8192
#define FBLKB   (NCH*ACHB)         // per row-block
// per weight chunk block: [Bhi 8KB | Blo 8KB]
#define WCHB    16384

// ---------------- mlp smem layout (bytes) ----------------
// ring: 2 slots x 24KB; slot = [Ahi 4K|Alo 4K|Bhi 8K|Blo 8K]
#define SLOTB    24576
#define OFF_RING 0                 // 49152
#define OFF_H0   49152             // [hi 16K|lo 16K] 64 rows x 256B, XOR swz
#define OFF_T1   81920             // same, 32KB
#define SMEM_TOTAL 114688
// overlays (after GEMM3):
#define OFF_F1   0                 // fp32 64x133 = 34048 (over ring)
#define OFF_WB   OFF_H0            // fp32 128x32 = 16384 (over H0, post-residual)
#define OFF_F2   OFF_T1            // fp32 64x36  = 9216  (over T1)
#define F1ST     133

// ---------------- global scratch ----------------
__device__ __align__(128) char g_fA [(size_t)NCTA*FBLKB];  // feat tiles
__device__ __align__(128) char g_wAt[NCH*WCHB];            // wA chunk tiles
__device__ __align__(128) char g_w1t[4*WCHB];
__device__ __align__(128) char g_w2t[4*WCHB];

// ---------------- helpers ----------------
__device__ __forceinline__ void split_bf16(float v, __nv_bfloat16& hi, __nv_bfloat16& lo) {
    hi = __float2bfloat16(v);
    lo = __float2bfloat16(v - __bfloat162float(hi));
}
__device__ __forceinline__ uint32_t pack_bf2(__nv_bfloat16 e0, __nv_bfloat16 e1) {
    return ((uint32_t)__bfloat16_as_ushort(e1) << 16) | (uint32_t)__bfloat16_as_ushort(e0);
}
__device__ __forceinline__ uint32_t smem_u32(const void* p) {
    return (uint32_t)__cvta_generic_to_shared(p);
}
__device__ __forceinline__ void mbar_init(uint32_t mbar, uint32_t cnt) {
    asm volatile("mbarrier.init.shared.b64 [%0], %1;" :: "r"(mbar), "r"(cnt) : "memory");
}
__device__ __forceinline__ void mbar_expect_tx(uint32_t mbar, uint32_t bytes) {
    asm volatile("mbarrier.arrive.expect_tx.shared.b64 _, [%0], %1;" :: "r"(mbar), "r"(bytes) : "memory");
}
__device__ __forceinline__ void mbar_wait(uint32_t mbar, uint32_t parity) {
    asm volatile(
        "{\n\t.reg .pred P;\n"
        "W%=:\n\t"
        "mbarrier.try_wait.parity.acquire.cta.shared::cta.b64 P, [%0], %1, 0x989680;\n\t"
        "@P bra D%=;\n\t"
        "bra W%=;\n"
        "D%=:\n\t}"
        :: "r"(mbar), "r"(parity) : "memory");
}
__device__ __forceinline__ void bulk_in(uint32_t dst, const void* src, uint32_t bytes, uint32_t mbar) {
    asm volatile(
        "cp.async.bulk.shared::cta.global.mbarrier::complete_tx::bytes [%0], [%1], %2, [%3];"
        :: "r"(dst), "l"(src), "r"(bytes), "r"(mbar) : "memory");
}
__device__ __forceinline__ void cp16(uint32_t dst, const void* src) {
    asm volatile("cp.async.cg.shared.global [%0], [%1], 16;" :: "r"(dst), "l"(src));
}
__device__ __forceinline__ void mma16816(float* c,
    uint32_t a0, uint32_t a1, uint32_t a2, uint32_t a3, uint32_t b0, uint32_t b1)
{
    asm volatile(
        "mma.sync.aligned.m16n8k16.row.col.f32.bf16.bf16.f32 "
        "{%0,%1,%2,%3}, {%4,%5,%6,%7}, {%8,%9}, {%0,%1,%2,%3};\n"
        : "+f"(c[0]), "+f"(c[1]), "+f"(c[2]), "+f"(c[3])
        : "r"(a0), "r"(a1), "r"(a2), "r"(a3), "r"(b0), "r"(b1));
}
// B tiles: 64B rows, byte-in-row rotated by 8*(n&7)
__device__ __forceinline__ uint32_t ldB(const char* base, int n, int kloc) {
    return *(const uint32_t*)(base + n * 64 + ((2 * kloc + 8 * (n & 7)) & 63));
}
// A chunk tiles: 64B rows, XOR key (r&3)<<4
__device__ __forceinline__ uint32_t ldA(const char* base, int r, int kB) {
    return *(const uint32_t*)(base + r * 64 + (kB ^ ((r & 3) << 4)));
}
// H/T tiles: 256B rows, XOR key (r&7)<<4
__device__ __forceinline__ uint32_t ldH(const char* base, int r, int kB) {
    return *(const uint32_t*)(base + r * 256 + (kB ^ ((r & 7) << 4)));
}
__device__ __forceinline__ void zero_acc(float (&acc)[2][4][4]) {
    #pragma unroll
    for (int a = 0; a < 2; ++a)
        #pragma unroll
        for (int b = 0; b < 4; ++b)
            #pragma unroll
            for (int c = 0; c < 4; ++c) acc[a][b][c] = 0.f;
}
// store split pair into a 256B-row tile (hi plane at base, lo at +16KB)
__device__ __forceinline__ void storeTile(char* base, int r, int col, float v0, float v1) {
    __nv_bfloat16 h0, l0, h1, l1;
    split_bf16(v0, h0, l0); split_bf16(v1, h1, l1);
    const int off = r * 256 + ((2 * col) ^ ((r & 7) << 4));
    *(uint32_t*)(base + off)         = pack_bf2(h0, h1);
    *(uint32_t*)(base + off + 16384) = pack_bf2(l0, l1);
}

// GEMM1 chunk (A 64B-row chunk tile, B 32-wide chunk)
__device__ __forceinline__ void gemm1_chunk(const char* slot,
    float (&acc)[2][4][4], int mb, int nb, int g, int tg)
{
    const char* Ah = slot;
    const char* Al = slot + 4096;
    const char* Bh = slot + 8192;
    const char* Bl = slot + 16384;
    #pragma unroll
    for (int kk = 0; kk < 2; ++kk) {
        const int kloc = kk * 16 + 2 * tg;
        const int kB = 2 * kloc;
        uint32_t ah[2][4], al[2][4];
        #pragma unroll
        for (int mt = 0; mt < 2; ++mt) {
            const int r = mb + mt * 16 + g;
            ah[mt][0] = ldA(Ah, r,     kB);
            ah[mt][1] = ldA(Ah, r + 8, kB);
            ah[mt][2] = ldA(Ah, r,     kB + 16);
            ah[mt][3] = ldA(Ah, r + 8, kB + 16);
            al[mt][0] = ldA(Al, r,     kB);
            al[mt][1] = ldA(Al, r + 8, kB);
            al[mt][2] = ldA(Al, r,     kB + 16);
            al[mt][3] = ldA(Al, r + 8, kB + 16);
        }
        #pragma unroll
        for (int nt = 0; nt < 4; ++nt) {
            const int n = nb + nt * 8 + g;
            const uint32_t bh0 = ldB(Bh, n, kloc), bh1 = ldB(Bh, n, kloc + 8);
            const uint32_t bl0 = ldB(Bl, n, kloc), bl1 = ldB(Bl, n, kloc + 8);
            #pragma unroll
            for (int mt = 0; mt < 2; ++mt) {
                mma16816(acc[mt][nt], ah[mt][0], ah[mt][1], ah[mt][2], ah[mt][3], bh0, bh1);
                mma16816(acc[mt][nt], ah[mt][0], ah[mt][1], ah[mt][2], ah[mt][3], bl0, bl1);
                mma16816(acc[mt][nt], al[mt][0], al[mt][1], al[mt][2], al[mt][3], bh0, bh1);
            }
        }
    }
}

// GEMM2/3 chunk (A = H0/T1 256B-row tile at kbase, B chunk in ring slot)
__device__ __forceinline__ void gemm23_chunk(const char* Abase, const char* slot,
    int kbase, float (&acc)[2][4][4], int mb, int nb, int g, int tg)
{
    const char* Ah = Abase;
    const char* Al = Abase + 16384;
    const char* Bh = slot + 8192;
    const char* Bl = slot + 16384;
    #pragma unroll
    for (int kk = 0; kk < 2; ++kk) {
        const int kloc = kk * 16 + 2 * tg;
        const int kB = 2 * (kbase + kloc);
        uint32_t ah[2][4], al[2][4];
        #pragma unroll
        for (int mt = 0; mt < 2; ++mt) {
            const int r = mb + mt * 16 + g;
            ah[mt][0] = ldH(Ah, r,     kB);
            ah[mt][1] = ldH(Ah, r + 8, kB);
            ah[mt][2] = ldH(Ah, r,     kB + 16);
            ah[mt][3] = ldH(Ah, r + 8, kB + 16);
            al[mt][0] = ldH(Al, r,     kB);
            al[mt][1] = ldH(Al, r + 8, kB);
            al[mt][2] = ldH(Al, r,     kB + 16);
            al[mt][3] = ldH(Al, r + 8, kB + 16);
        }
        #pragma unroll
        for (int nt = 0; nt < 4; ++nt) {
            const int n = nb + nt * 8 + g;
            const uint32_t bh0 = ldB(Bh, n, kloc), bh1 = ldB(Bh, n, kloc + 8);
            const uint32_t bl0 = ldB(Bl, n, kloc), bl1 = ldB(Bl, n, kloc + 8);
            #pragma unroll
            for (int mt = 0; mt < 2; ++mt) {
                mma16816(acc[mt][nt], ah[mt][0], ah[mt][1], ah[mt][2], ah[mt][3], bh0, bh1);
                mma16816(acc[mt][nt], ah[mt][0], ah[mt][1], ah[mt][2], ah[mt][3], bl0, bl1);
                mma16816(acc[mt][nt], al[mt][0], al[mt][1], al[mt][2], al[mt][3], bh0, bh1);
            }
        }
    }
}

// ---------------- kernel 1: feat (+ merged presplit) ----------------
__global__ __launch_bounds__(256) void feat_presplit_kernel(
    const float* __restrict__ x,
    const float* __restrict__ w_step, const float* __restrict__ b_step,
    const float* __restrict__ wA, const float* __restrict__ w1,
    const float* __restrict__ w2)
{
    const int tid = threadIdx.x;

    if (blockIdx.x >= BATCH) {
        const int id = (blockIdx.x - BATCH) * 256 + tid;
        if (id < 77824) {                       // wA: 128 x 608 (zero-padded k>=600)
            const int n = id / KP, k = id % KP;
            const float v = (k < FK) ? __ldg(wA + n * FK + k) : 0.f;
            __nv_bfloat16 h, l; split_bf16(v, h, l);
            const int c = k >> 5, kl = k & 31;
            const int off = c * WCHB + n * 64 + ((2 * kl + 8 * (n & 7)) & 63);
            *(__nv_bfloat16*)(g_wAt + off)        = h;
            *(__nv_bfloat16*)(g_wAt + off + 8192) = l;
        } else if (id < 94208) {                // w1: 128 x 128
            const int t = id - 77824, n = t >> 7, k = t & 127;
            __nv_bfloat16 h, l; split_bf16(__ldg(w1 + n * 128 + k), h, l);
            const int c = k >> 5, kl = k & 31;
            const int off = c * WCHB + n * 64 + ((2 * kl + 8 * (n & 7)) & 63);
            *(__nv_bfloat16*)(g_w1t + off)        = h;
            *(__nv_bfloat16*)(g_w1t + off + 8192) = l;
        } else if (id < 110592) {               // w2
            const int t = id - 94208, n = t >> 7, k = t & 127;
            __nv_bfloat16 h, l; split_bf16(__ldg(w2 + n * 128 + k), h, l);
            const int c = k >> 5, kl = k & 31;
            const int off = c * WCHB + n * 64 + ((2 * kl + 8 * (n & 7)) & 63);
            *(__nv_bfloat16*)(g_w2t + off)        = h;
            *(__nv_bfloat16*)(g_w2t + off + 8192) = l;
        }
        return;
    }

    // ---- feat: one block per batch row ----
    __shared__ float sx[ROWLEN];
    __shared__ float ss[QS];

    const int row = blockIdx.x;
    const float4* src = (const float4*)(x + (size_t)row * ROWLEN);
    const uint32_t sxu = smem_u32(sx);
    // cp.async streaming: no register round-trip, deep MLP
    for (int i = tid; i < ROW4; i += 256) cp16(sxu + i * 16, src + i);
    asm volatile("cp.async.commit_group;" ::: "memory");

    const float w0 = __ldg(w_step + 0), w1c = __ldg(w_step + 1), w2c = __ldg(w_step + 2),
                w3 = __ldg(w_step + 3), w4 = __ldg(w_step + 4), w5 = __ldg(w_step + 5),
                w6 = __ldg(w_step + 6), bs = __ldg(b_step);
    asm volatile("cp.async.wait_group 0;" ::: "memory");
    __syncthreads();

    for (int q = tid; q < QS; q += 256) {
        const float* p = sx + q * FD;
        float v = fmaf(p[0], w0, fmaf(p[1], w1c, fmaf(p[2], w2c,
                  fmaf(p[3], w3, fmaf(p[4], w4, fmaf(p[5], w5, p[6] * w6))))));
        ss[q] = v + bs;
    }
    __syncthreads();

    const int blk  = row >> 6;
    const int rloc = row & 63;
    char* fbase = g_fA + (size_t)blk * FBLKB;
    const int rbase = rloc * 64;
    const int key   = (rloc & 3) << 4;

    for (int t = tid; t < KP / 2; t += 256) {    // 304 feature pairs
        const int j0 = 2 * t;
        float v0 = 0.f, v1 = 0.f;
        if (j0 < FK) {
            {
                const int bl = j0 / 5, off = j0 % 5;
                const float* p = ss + off + bl * 10;
                float m = p[0];
                #pragma unroll
                for (int i = 1; i < 10; ++i) m = fmaxf(m, p[i]);
                v0 = m;
            }
            {
                const int j1 = j0 + 1;
                const int bl = j1 / 5, off = j1 % 5;
                const float* p = ss + off + bl * 10;
                float m = p[0];
                #pragma unroll
                for (int i = 1; i < 10; ++i) m = fmaxf(m, p[i]);
                v1 = m;
            }
        }
        __nv_bfloat16 h0, l0, h1, l1;
        split_bf16(v0, h0, l0);
        split_bf16(v1, h1, l1);
        const int c = j0 >> 5, kl = j0 & 31;
        const int off = c * ACHB + rbase + ((2 * kl) ^ key);
        *(uint32_t*)(fbase + off)        = pack_bf2(h0, h1);
        *(uint32_t*)(fbase + off + 4096) = pack_bf2(l0, l1);
    }
}

// ---------------- kernel 2: MLP, streamed ring, 2 CTA/SM ----------------
__global__ __launch_bounds__(256, 2) void mlp_kernel(
    const float* __restrict__ bA, const float* __restrict__ b1,
    const float* __restrict__ b2, const float* __restrict__ bB,
    const float* __restrict__ wB, const float* __restrict__ wC,
    const float* __restrict__ bC, float* __restrict__ out)
{
    extern __shared__ __align__(16) char smem[];
    __shared__ __align__(8) unsigned long long s_mb[2];

    const int tid  = threadIdx.x;
    const int wid  = tid >> 5;
    const int lane = tid & 31;
    const int g    = lane >> 2;
    const int tg   = lane & 3;
    const int mb   = (wid & 1) * 32;
    const int nb   = (wid >> 1) * 32;
    const int row0 = blockIdx.x * RPC;
    const uint32_t smb = smem_u32(smem);

    if (tid == 0) {
        mbar_init(smem_u32(&s_mb[0]), 1);
        mbar_init(smem_u32(&s_mb[1]), 1);
    }
    __syncthreads();

    // fetch chunk cnt into ring slot cnt&1 (tid 0 only)
    auto fetch = [&](int cnt) {
        const int s = cnt & 1;
        const uint32_t m = smem_u32(&s_mb[s]);
        const uint32_t slot = smb + OFF_RING + s * SLOTB;
        if (cnt < NCH) {
            mbar_expect_tx(m, ACHB + WCHB);
            bulk_in(slot,        g_fA + (size_t)blockIdx.x * FBLKB + cnt * ACHB, ACHB, m);
            bulk_in(slot + 8192, g_wAt + cnt * WCHB,                             WCHB, m);
        } else if (cnt < NCH + 4) {
            mbar_expect_tx(m, WCHB);
            bulk_in(slot + 8192, g_w1t + (cnt - NCH) * WCHB, WCHB, m);
        } else {
            mbar_expect_tx(m, WCHB);
            bulk_in(slot + 8192, g_w2t + (cnt - NCH - 4) * WCHB, WCHB, m);
        }
    };

    if (tid == 0) { fetch(0); fetch(1); }

    float acc[2][4][4];

    // ---------- GEMM1: D1 = feat @ wA^T (19 chunks) ----------
    zero_acc(acc);
    for (int c = 0; c < NCH; ++c) {
        mbar_wait(smem_u32(&s_mb[c & 1]), (c >> 1) & 1);
        gemm1_chunk(smem + OFF_RING + (c & 1) * SLOTB, acc, mb, nb, g, tg);
        __syncthreads();
        if (tid == 0 && c + 2 < NCHT) fetch(c + 2);
    }

    // ---------- epilogue 1: H0 = relu(D1 + bA) split tiles ----------
    char* H0 = smem + OFF_H0;
    #pragma unroll
    for (int mt = 0; mt < 2; ++mt) {
        const int r0 = mb + mt * 16 + g;
        #pragma unroll
        for (int nt = 0; nt < 4; ++nt) {
            const int col = nb + nt * 8 + 2 * tg;
            const float bb0 = __ldg(bA + col), bb1 = __ldg(bA + col + 1);
            storeTile(H0, r0,     col, fmaxf(acc[mt][nt][0] + bb0, 0.f),
                                       fmaxf(acc[mt][nt][1] + bb1, 0.f));
            storeTile(H0, r0 + 8, col, fmaxf(acc[mt][nt][2] + bb0, 0.f),
                                       fmaxf(acc[mt][nt][3] + bb1, 0.f));
        }
    }
    __syncthreads();

    // ---------- GEMM2: D2 = h0 @ w1^T (chunks 19..22) ----------
    zero_acc(acc);
    for (int j = 0; j < 4; ++j) {
        const int cnt = NCH + j;
        mbar_wait(smem_u32(&s_mb[cnt & 1]), (cnt >> 1) & 1);
        gemm23_chunk(H0, smem + OFF_RING + (cnt & 1) * SLOTB, j * 32, acc, mb, nb, g, tg);
        __syncthreads();
        if (tid == 0 && cnt + 2 < NCHT) fetch(cnt + 2);
    }

    // ---------- epilogue 2: T1 = relu(D2 + b1) split tiles ----------
    char* T1 = smem + OFF_T1;
    #pragma unroll
    for (int mt = 0; mt < 2; ++mt) {
        const int r0 = mb + mt * 16 + g;
        #pragma unroll
        for (int nt = 0; nt < 4; ++nt) {
            const int col = nb + nt * 8 + 2 * tg;
            const float bb0 = __ldg(b1 + col), bb1 = __ldg(b1 + col + 1);
            storeTile(T1, r0,     col, fmaxf(acc[mt][nt][0] + bb0, 0.f),
                                       fmaxf(acc[mt][nt][1] + bb1, 0.f));
            storeTile(T1, r0 + 8, col, fmaxf(acc[mt][nt][2] + bb0, 0.f),
                                       fmaxf(acc[mt][nt][3] + bb1, 0.f));
        }
    }
    __syncthreads();

    // ---------- GEMM3: D3 = t1 @ w2^T (chunks 23..26) ----------
    zero_acc(acc);
    for (int j = 0; j < 4; ++j) {
        const int cnt = NCH + 4 + j;
        mbar_wait(smem_u32(&s_mb[cnt & 1]), (cnt >> 1) & 1);
        gemm23_chunk(T1, smem + OFF_RING + (cnt & 1) * SLOTB, j * 32, acc, mb, nb, g, tg);
        __syncthreads();
        if (tid == 0 && cnt + 2 < NCHT) fetch(cnt + 2);   // keep ring fed to the end
    }

    // ---------- epilogue 3: F1 = relu(h0 + D3 + b2) fp32 (over ring) ----------
    {
        float* F1 = (float*)(smem + OFF_F1);
        #pragma unroll
        for (int mt = 0; mt < 2; ++mt) {
            #pragma unroll
            for (int nt = 0; nt < 4; ++nt) {
                const int col = nb + nt * 8 + 2 * tg;
                const float bb0 = __ldg(b2 + col), bb1 = __ldg(b2 + col + 1);
                #pragma unroll
                for (int half = 0; half < 2; ++half) {
                    const int r = mb + mt * 16 + g + half * 8;
                    const int off = r * 256 + ((2 * col) ^ ((r & 7) << 4));
                    const uint32_t ph = *(uint32_t*)(H0 + off);
                    const uint32_t pl = *(uint32_t*)(H0 + off + 16384);
                    const float h0v = __bfloat162float(__ushort_as_bfloat16((unsigned short)(ph & 0xFFFF)))
                                    + __bfloat162float(__ushort_as_bfloat16((unsigned short)(pl & 0xFFFF)));
                    const float h1v = __bfloat162float(__ushort_as_bfloat16((unsigned short)(ph >> 16)))
                                    + __bfloat162float(__ushort_as_bfloat16((unsigned short)(pl >> 16)));
                    const float a0 = acc[mt][nt][half * 2 + 0];
                    const float a1 = acc[mt][nt][half * 2 + 1];
                    F1[r * F1ST + col]     = fmaxf(h0v + a0 + bb0, 0.f);
                    F1[r * F1ST + col + 1] = fmaxf(h1v + a1 + bb1, 0.f);
                }
            }
        }
    }
    __syncthreads();

    // ---------- wB transpose copy (over H0, now dead) ----------
    {
        float* wBs = (float*)(smem + OFF_WB);
        #pragma unroll 4
        for (int i = tid; i < 4096; i += 256) {
            const int k = i >> 5, n = i & 31;
            wBs[i] = __ldg(wB + n * 128 + k);
        }
    }
    __syncthreads();

    // ---------- stage 3: h2 = relu(h1 @ wB^T + bB) scalar fp32 ----------
    {
        const float* F1 = (const float*)(smem + OFF_F1);
        const float* wBs = (const float*)(smem + OFF_WB);
        float* F2 = (float*)(smem + OFF_F2);
        const int r  = tid >> 2;
        const int n0 = (tid & 3) * 8;
        float a3[8];
        #pragma unroll
        for (int i = 0; i < 8; ++i) a3[i] = 0.f;
        #pragma unroll 4
        for (int k = 0; k < 128; ++k) {
            const float hv = F1[r * F1ST + k];
            const float4 q0 = *(const float4*)(wBs + k * 32 + n0);
            const float4 q1 = *(const float4*)(wBs + k * 32 + n0 + 4);
            a3[0] = fmaf(hv, q0.x, a3[0]); a3[1] = fmaf(hv, q0.y, a3[1]);
            a3[2] = fmaf(hv, q0.z, a3[2]); a3[3] = fmaf(hv, q0.w, a3[3]);
            a3[4] = fmaf(hv, q1.x, a3[4]); a3[5] = fmaf(hv, q1.y, a3[5]);
            a3[6] = fmaf(hv, q1.z, a3[6]); a3[7] = fmaf(hv, q1.w, a3[7]);
        }
        #pragma unroll
        for (int n = 0; n < 8; ++n)
            F2[r * 36 + n0 + n] = fmaxf(a3[n] + __ldg(bB + n0 + n), 0.f);
    }
    __syncthreads();

    // ---------- stage 4: logits ----------
    if (tid < 128) {
        const float* F2 = (const float*)(smem + OFF_F2);
        const int r = tid >> 1, c = tid & 1;
        float s = __ldg(bC + c);
        #pragma unroll
        for (int k = 0; k < 32; ++k)
            s = fmaf(F2[r * 36 + k], __ldg(wC + c * 32 + k), s);
        out[(size_t)(row0 + r) * 2 + c] = s;
    }
}

// ---------------- launch ----------------
extern "C" void kernel_launch(void* const* d_in, const int* in_sizes, int n_in,
                              void* d_out, int out_size)
{
    const float* x      = (const float*)d_in[0];
    const float* w_step = (const float*)d_in[1];
    const float* b_step = (const float*)d_in[2];
    const float* wA     = (const float*)d_in[3];
    const float* bA     = (const float*)d_in[4];
    const float* w1     = (const float*)d_in[5];
    const float* b1     = (const float*)d_in[6];
    const float* w2     = (const float*)d_in[7];
    const float* b2     = (const float*)d_in[8];
    const float* wB     = (const float*)d_in[9];
    const float* bB     = (const float*)d_in[10];
    const float* wC     = (const float*)d_in[11];
    const float* bC     = (const float*)d_in[12];
    float* out          = (float*)d_out;

    static bool attr_set = false;
    if (!attr_set) {
        cudaFuncSetAttribute(mlp_kernel, cudaFuncAttributeMaxDynamicSharedMemorySize, SMEM_TOTAL);
        attr_set = true;
    }

    feat_presplit_kernel<<<BATCH + 432, 256>>>(x, w_step, b_step, wA, w1, w2);
    mlp_kernel<<<NCTA, 256, SMEM_TOTAL>>>(bA, b1, b2, bB, wB, wC, bC, out);
}